// round 13
// baseline (speedup 1.0000x reference)
#include <cuda_runtime.h>
#include <cuda_fp16.h>
#include <cstdint>

#define T_  256
#define NN  4000
#define DM  178
#define DI  46
#define H_  64
#define DH  64
#define FF  110   // DI + H
#define G4  256   // 4*H
#define TILE 128
#define NTILES (T_ * 32)   // 8192
#define GRID_MLP 295       // leave one CTA slot free for the resident k_lstm CTA

typedef unsigned long long u64;

// ---------- device scratch ----------
__device__ float g_XZ[T_ * G4];
__device__ float g_macro1[T_ * DH];
__device__ float g_sum[T_];
__device__ float g_cnt[T_];
__device__ int   g_mask_kind;     // 0=uint8/bool, 1=int32, 2=float32
__device__ int   g_prog[8 * 32];  // striped chunk-progress flags (reset by k_prep)

// ---------- packed f32x2 helpers ----------
__device__ __forceinline__ u64 pk2(float lo, float hi) {
    u64 r; asm("mov.b64 %0, {%1, %2};" : "=l"(r) : "f"(lo), "f"(hi)); return r;
}
__device__ __forceinline__ u64 ffma2(u64 a, u64 b, u64 c) {
    u64 d; asm("fma.rn.f32x2 %0, %1, %2, %3;" : "=l"(d) : "l"(a), "l"(b), "l"(c)); return d;
}
__device__ __forceinline__ float2 up2(u64 a) {
    float2 f; asm("mov.b64 {%0, %1}, %2;" : "=f"(f.x), "=f"(f.y) : "l"(a)); return f;
}

// ---------- activations ----------
__device__ __forceinline__ float sigm(float x) {
    float e = exp2f(-1.44269504088896340736f * x);
    return __fdividef(1.0f, 1.0f + e);
}
__device__ __forceinline__ float tanh_(float x) {
    float a = fabsf(x);
    float e = exp2f(-2.88539008177792681472f * a);
    float r = __fdividef(1.0f - e, 1.0f + e);
    return copysignf(r, x);
}

// ---------- warp MMA helpers ----------
__device__ __forceinline__ uint32_t smem_u32(const void* p) {
    uint32_t a;
    asm("{ .reg .u64 t; cvta.to.shared.u64 t, %1; cvt.u32.u64 %0, t; }" : "=r"(a) : "l"(p));
    return a;
}
__device__ __forceinline__ void ldsm4(uint32_t* r, uint32_t addr) {
    asm volatile("ldmatrix.sync.aligned.m8n8.x4.shared.b16 {%0,%1,%2,%3}, [%4];"
        : "=r"(r[0]), "=r"(r[1]), "=r"(r[2]), "=r"(r[3]) : "r"(addr));
}
__device__ __forceinline__ void mma16816(float* d, const uint32_t* a, const uint32_t* b) {
    asm volatile("mma.sync.aligned.m16n8k16.row.col.f32.f16.f16.f32 "
        "{%0,%1,%2,%3}, {%4,%5,%6,%7}, {%8,%9}, {%0,%1,%2,%3};"
        : "+f"(d[0]), "+f"(d[1]), "+f"(d[2]), "+f"(d[3])
        : "r"(a[0]), "r"(a[1]), "r"(a[2]), "r"(a[3]), "r"(b[0]), "r"(b[1]));
}
__device__ __forceinline__ uint32_t pkhf(__half a, __half b) {
    return ((uint32_t)__half_as_ushort(b) << 16) | (uint32_t)__half_as_ushort(a);
}
__device__ __forceinline__ void split_hf(float x, __half& h, __half& l) {
    h = __float2half_rn(x);
    l = __float2half_rn(x - __half2float(h));
}
// row/chunk -> byte offset: 144B row stride, chunk rotation mod 9
__device__ __forceinline__ uint32_t roff(int r, int c) {
    return (uint32_t)(r * 144 + ((c + (r >> 3)) % 9) * 16);
}
__device__ __forceinline__ void cp16(uint32_t saddr, const void* gaddr) {
    asm volatile("cp.async.cg.shared.global [%0], [%1], 16;" :: "r"(saddr), "l"(gaddr));
}
__device__ __forceinline__ int ld_acq(const int* p) {
    int v; asm volatile("ld.acquire.gpu.global.b32 %0, [%1];" : "=r"(v) : "l"(p)); return v;
}
__device__ __forceinline__ void st_rel(int* p, int v) {
    asm volatile("st.release.gpu.global.b32 [%0], %1;" :: "l"(p), "r"(v) : "memory");
}

// ---------- K1: XZ with smem-cached W slice (64 blocks) + mask detect + flag reset ----------
#define PREP_SMEM ((64 * 185 + 16 * DM) * 4)
__global__ void __launch_bounds__(256) k_prep(const float* __restrict__ macro,
                                              const float* __restrict__ W_ih,
                                              const float* __restrict__ b_ih,
                                              const float* __restrict__ b_hh,
                                              const unsigned char* __restrict__ masks) {
    extern __shared__ float psm[];
    float* Wsm = psm;                 // [64][185]
    float* xs  = psm + 64 * 185;      // [16][178]
    const int tid = threadIdx.x;
    const int gg = blockIdx.x & 3, tg = blockIdx.x >> 2;

    for (int idx = tid; idx < 64 * DM; idx += 256) {
        int g = idx / DM, k = idx - g * DM;
        Wsm[g * 185 + k] = W_ih[(size_t)(gg * 64 + g) * DM + k];
    }
    for (int idx = tid; idx < 16 * DM; idx += 256) {
        int tt = idx / DM, k = idx - tt * DM;
        xs[tt * DM + k] = macro[(size_t)(tg * 16 + tt) * DM + k];
    }
    if (gg == 0 && tid < 16) {
        g_sum[tg * 16 + tid] = 0.f;
        g_cnt[tg * 16 + tid] = 0.f;
    }
    if (blockIdx.x == 1 && tid < 8) g_prog[tid * 32] = -1;   // reset chunk flags each replay
    __syncthreads();

    const int g = tid & 63, tq = tid >> 6;
    const float bsum = b_ih[gg * 64 + g] + b_hh[gg * 64 + g];
    const float* wrow = Wsm + g * 185;
    for (int tt = tq; tt < 16; tt += 4) {
        const float* xr = xs + tt * DM;
        float a0 = 0.f, a1 = 0.f, a2 = 0.f, a3 = 0.f;
#pragma unroll 4
        for (int k = 0; k < 176; k += 4) {
            a0 = fmaf(wrow[k],     xr[k],     a0);
            a1 = fmaf(wrow[k + 1], xr[k + 1], a1);
            a2 = fmaf(wrow[k + 2], xr[k + 2], a2);
            a3 = fmaf(wrow[k + 3], xr[k + 3], a3);
        }
        a0 = fmaf(wrow[176], xr[176], a0);
        a1 = fmaf(wrow[177], xr[177], a1);
        g_XZ[(tg * 16 + tt) * G4 + gg * 64 + g] = ((a0 + a1) + (a2 + a3)) + bsum;
    }

    if (blockIdx.x == 0) {
        __shared__ int s_any, s_flt;
        if (tid == 0) { s_any = 0; s_flt = 0; }
        __syncthreads();
        int ta = 0, tf = 0;
        for (int j = tid; j < 1024; j += 256) {
            unsigned char c1 = masks[4 * j + 1], c2 = masks[4 * j + 2], c3 = masks[4 * j + 3];
            if (c1 | c2 | c3) ta = 1;
            if (c3 == 0x3F) tf = 1;
        }
        if (ta) atomicOr(&s_any, 1);
        if (tf) atomicOr(&s_flt, 1);
        __syncthreads();
        if (tid == 0) g_mask_kind = s_flt ? 2 : (s_any ? 0 : 1);
    }
    // no early trigger: dependents wait for full completion
}

// ---------- K2: chunked LSTM scan producer (8 chunks of 32 t) ----------
#define LSTM_SMEM (((T_ + 1) * H_ + 64 * 66) * 4)
__global__ void __launch_bounds__(256, 1) k_lstm(const float* __restrict__ W_hh,
                                                 const float* __restrict__ W1,
                                                 const float* __restrict__ b1) {
    extern __shared__ float hs[];
    float* W1s = hs + (T_ + 1) * H_;   // [64][66] padded
    const int tid = threadIdx.x;
    const int lane = tid & 31;
    const bool active = tid < 128;
    const bool roleA = (lane < 16);
    const int u = (tid >> 5) * 16 + (lane & 15);
    const int r0 = roleA ? u : (64 + u);
    const int r1 = roleA ? (128 + u) : (192 + u);

    cudaGridDependencySynchronize();                 // prep fully complete
    if (tid == 0) cudaTriggerProgrammaticLaunchCompletion();   // release k_mlp NOW

    u64 w0[32], w1[32];
    if (active) {
        const float4* A = (const float4*)(W_hh + (size_t)r0 * H_);
        const float4* B = (const float4*)(W_hh + (size_t)r1 * H_);
#pragma unroll
        for (int k = 0; k < 16; k++) {
            float4 va = A[k], vb = B[k];
            w0[2 * k] = pk2(va.x, va.y); w0[2 * k + 1] = pk2(va.z, va.w);
            w1[2 * k] = pk2(vb.x, vb.y); w1[2 * k + 1] = pk2(vb.z, vb.w);
        }
    }
    for (int idx = tid; idx < 64 * 64; idx += 256) {
        int o = idx >> 6, k = idx & 63;
        W1s[o * 66 + k] = W1[o * FF + DI + k];
    }
    if (tid < H_) hs[tid] = 0.f;
    float c = 0.f;
    float z0 = active ? g_XZ[r0] : 0.f;
    float z1 = active ? g_XZ[r1] : 0.f;
    __syncthreads();

    const u64 one = pk2(1.f, 1.f);
    const int o = tid & 63, tq = tid >> 6;
    const u64* wmr = (const u64*)(W1s + o * 66);
    const float b1v = b1[o];

    for (int ck = 0; ck < 8; ck++) {
        // ---- scan 32 steps ----
        for (int ts = 0; ts < 32; ts++) {
            const int t = ck * 32 + ts;
            if (active) {
                const u64* h64 = (const u64*)(hs + t * H_);
                u64 a0 = pk2(0.f, 0.f), a1 = a0, b0 = a0, b1a = a0;
#pragma unroll
                for (int k = 0; k < 32; k += 2) {
                    a0  = ffma2(w0[k],     h64[k],     a0);
                    a1  = ffma2(w0[k + 1], h64[k + 1], a1);
                    b0  = ffma2(w1[k],     h64[k],     b0);
                    b1a = ffma2(w1[k + 1], h64[k + 1], b1a);
                }
                a0 = ffma2(one, a1, a0);
                b0 = ffma2(one, b1a, b0);
                float2 sa = up2(a0), sb = up2(b0);
                float z0f = z0 + sa.x + sa.y;
                float z1f = z1 + sb.x + sb.y;
                if (t + 1 < T_) {
                    z0 = g_XZ[(t + 1) * G4 + r0];
                    z1 = g_XZ[(t + 1) * G4 + r1];
                }
                float p = 0.f;
                if (roleA) p = sigm(z0f) * tanh_(z1f);     // i*g
                p = __shfl_xor_sync(0xffffffffu, p, 16);
                if (!roleA) {
                    float fv = sigm(z0f), ov = sigm(z1f);
                    c = fmaf(fv, c, p);
                    hs[(t + 1) * H_ + u] = ov * tanh_(c);
                }
            }
            __syncthreads();
        }
        // ---- macro1 for this chunk (W1m from smem) ----
        for (int tt = ck * 32 + tq; tt < ck * 32 + 32; tt += 4) {
            const u64* h64 = (const u64*)(hs + (tt + 1) * H_);
            u64 a0 = pk2(0.f, 0.f), a1 = a0, a2 = a0, a3 = a0;
#pragma unroll
            for (int k = 0; k < 32; k += 4) {
                a0 = ffma2(wmr[k],     h64[k],     a0);
                a1 = ffma2(wmr[k + 1], h64[k + 1], a1);
                a2 = ffma2(wmr[k + 2], h64[k + 2], a2);
                a3 = ffma2(wmr[k + 3], h64[k + 3], a3);
            }
            a0 = ffma2(one, a1, a0);
            a2 = ffma2(one, a3, a2);
            float2 s0 = up2(a0), s2 = up2(a2);
            g_macro1[tt * DH + o] = ((s0.x + s0.y) + (s2.x + s2.y)) + b1v;
        }
        // ---- publish chunk ----
        __threadfence();
        __syncthreads();
        if (tid < 8) st_rel(&g_prog[tid * 32], ck);
    }
}

// ---------- K4: warp-MMA fused MLP; overlapped with k_lstm via chunk flags ----------
#define SM_XHI 0
#define SM_XLO 18432
#define SM_W1H 36864
#define SM_W1L 46080
#define SM_W2H 55296
#define SM_W2L 64512
#define SM_RAW 73728      // 4 warp slabs x 5888B
#define SM_WROW (SM_RAW + 23552)
#define SMEM_MLP (SM_WROW + 512)

__device__ __forceinline__ void do_layer1(
    uint32_t sb, const float* iv, float acc[2][8][4],
    int wid, int a_ro, int a_co, int b_ro, int b_co)
{
#pragma unroll
    for (int mi = 0; mi < 2; mi++)
#pragma unroll
        for (int ni = 0; ni < 8; ni++) {
            acc[mi][ni][0] = iv[2 * ni];
            acc[mi][ni][1] = iv[2 * ni + 1];
            acc[mi][ni][2] = iv[2 * ni];
            acc[mi][ni][3] = iv[2 * ni + 1];
        }
#pragma unroll
    for (int kc = 0; kc < 3; kc++) {
        uint32_t ah[2][4], al[2][4], bh[4][4], bl[4][4];
#pragma unroll
        for (int mi = 0; mi < 2; mi++) {
            uint32_t off = roff(wid * 32 + mi * 16 + a_ro, 2 * kc + a_co);
            ldsm4(ah[mi], sb + SM_XHI + off);
            ldsm4(al[mi], sb + SM_XLO + off);
        }
#pragma unroll
        for (int np = 0; np < 4; np++) {
            uint32_t off = roff(np * 16 + b_ro, 2 * kc + b_co);
            ldsm4(bh[np], sb + SM_W1H + off);
            ldsm4(bl[np], sb + SM_W1L + off);
        }
#pragma unroll
        for (int mi = 0; mi < 2; mi++)
#pragma unroll
            for (int ni = 0; ni < 8; ni++)
                mma16816(acc[mi][ni], ah[mi], &bh[ni >> 1][(ni & 1) * 2]);
#pragma unroll
        for (int mi = 0; mi < 2; mi++)
#pragma unroll
            for (int ni = 0; ni < 8; ni++)
                mma16816(acc[mi][ni], al[mi], &bh[ni >> 1][(ni & 1) * 2]);
#pragma unroll
        for (int mi = 0; mi < 2; mi++)
#pragma unroll
            for (int ni = 0; ni < 8; ni++)
                mma16816(acc[mi][ni], ah[mi], &bl[ni >> 1][(ni & 1) * 2]);
    }
}

__global__ void __launch_bounds__(128, 2)
k_mlp(const float* __restrict__ indiv, const unsigned char* __restrict__ mask_raw,
      const float* __restrict__ rets, const float* __restrict__ W1,
      const float* __restrict__ W2, const float* __restrict__ b2,
      const float* __restrict__ W3, const float* __restrict__ b3,
      float* __restrict__ out_w)
{
    extern __shared__ char sm[];
    const uint32_t sb = smem_u32(sm);
    float* wrow = (float*)(sm + SM_WROW);

    const int tid = threadIdx.x;
    const int wid = tid >> 5, lane = tid & 31;
    const int lq = lane & 7, qq = lane >> 3;
    const int a_ro = lq + ((qq & 1) << 3), a_co = qq >> 1;
    const int b_ro = lq + ((qq >> 1) << 3), b_co = qq & 1;
    const int cpair = (lane & 3) * 2;

    // ---- preamble (input-only, overlaps producer) ----
    for (int idx = tid; idx < 64 * 64; idx += 128) {
        int n = idx >> 6, k = idx & 63;
        float v1 = (k < DI) ? W1[n * FF + k] : 0.f;
        float v2 = W2[idx];
        uint32_t o = roff(n, k >> 3) + (k & 7) * 2;
        __half h, l;
        split_hf(v1, h, l);
        *(__half*)(sm + SM_W1H + o) = h;
        *(__half*)(sm + SM_W1L + o) = l;
        split_hf(v2, h, l);
        *(__half*)(sm + SM_W2H + o) = h;
        *(__half*)(sm + SM_W2L + o) = l;
    }
    float b2v[16], w3v[16];
#pragma unroll
    for (int ni = 0; ni < 8; ni++) {
        b2v[2 * ni]     = b2[ni * 8 + cpair];
        b2v[2 * ni + 1] = b2[ni * 8 + cpair + 1];
        w3v[2 * ni]     = W3[ni * 8 + cpair];
        w3v[2 * ni + 1] = W3[ni * 8 + cpair + 1];
    }
    const float b3v = b3[0];

    float acc[2][8][4];
    const uint32_t slab = sb + SM_RAW + wid * 5888;
    const float* rawf = (const float*)(sm + SM_RAW + wid * 5888);

    auto stage = [&](int tile) {
        const int t = tile >> 5;
        const int p0 = (tile & 31) * TILE;
        if ((p0 + wid * 32) < NN) {
            const float4* gsrc = (const float4*)(indiv + ((size_t)t * NN + p0 + wid * 32) * DI);
#pragma unroll
            for (int i = lane; i < 368; i += 32)
                cp16(slab + (uint32_t)i * 16, gsrc + i);
            asm volatile("cp.async.commit_group;" ::: "memory");
        }
    };

    if (blockIdx.x < NTILES) stage(blockIdx.x);
    __syncthreads();

    cudaGridDependencySynchronize();   // k_lstm triggered (=> prep complete); macro1 via flags
    const int mask_kind = g_mask_kind;

    const int* stripe = &g_prog[(blockIdx.x & 7) * 32];
    int seen = -1;

    for (int tile = blockIdx.x; tile < NTILES; tile += gridDim.x) {
        const int t = tile >> 5;
        const int p0 = (tile & 31) * TILE;
        const int pg = p0 + tid;
        const bool valid = pg < NN;

        // wait for macro1 chunk (register-cached, striped, backoff)
        const int ck = t >> 5;
        if (seen < ck) {
            int sl = 512;
            while ((seen = ld_acq(stripe)) < ck) {
                __nanosleep(sl);
                if (sl < 8192) sl <<= 1;
            }
        }

        float m1v[16];
#pragma unroll
        for (int ni = 0; ni < 8; ni++) {
            m1v[2 * ni]     = g_macro1[t * 64 + ni * 8 + cpair];
            m1v[2 * ni + 1] = g_macro1[t * 64 + ni * 8 + cpair + 1];
        }
        asm volatile("cp.async.wait_group 0;" ::: "memory");
        __syncwarp();

        // ---- split own row to fp16 hi/lo, swizzled STS (float2 raw reads) ----
        {
            const float2* rp2 = (const float2*)(rawf + lane * DI);
            const uint32_t rbase = (uint32_t)(tid * 144);
            const int rot0 = tid >> 3;
#pragma unroll
            for (int c = 0; c < 6; c++) {
                uint32_t hw[4], lw[4];
#pragma unroll
                for (int jp = 0; jp < 4; jp++) {
                    int pi = c * 4 + jp;
                    float2 v = (pi < 23) ? rp2[pi] : make_float2(0.f, 0.f);
                    if (!valid) v = make_float2(0.f, 0.f);
                    __half h0, l0, h1, l1;
                    split_hf(v.x, h0, l0);
                    split_hf(v.y, h1, l1);
                    hw[jp] = pkhf(h0, h1);
                    lw[jp] = pkhf(l0, l1);
                }
                uint32_t off = rbase + (uint32_t)(((c + rot0) % 9) * 16);
                *(uint4*)(sm + SM_XHI + off) = make_uint4(hw[0], hw[1], hw[2], hw[3]);
                *(uint4*)(sm + SM_XLO + off) = make_uint4(lw[0], lw[1], lw[2], lw[3]);
            }
        }
        __syncwarp();

        // ---- layer 1: K=48 ----
        do_layer1(sb, m1v, acc, wid, a_ro, a_co, b_ro, b_co);

        // ---- prefetch NEXT tile's X into the dead RAW slab ----
        {
            int nxt = tile + gridDim.x;
            if (nxt < NTILES) stage(nxt);
        }

        // ---- C->A register identity: relu + split layer-1 acc into layer-2 A frags ----
        uint32_t ah2[2][4][4], al2[2][4][4];
#pragma unroll
        for (int mi = 0; mi < 2; mi++)
#pragma unroll
            for (int kc = 0; kc < 4; kc++)
#pragma unroll
                for (int h2 = 0; h2 < 2; h2++) {
                    const int ni = 2 * kc + h2;
                    float r0 = fmaxf(acc[mi][ni][0], 0.f);
                    float r1 = fmaxf(acc[mi][ni][1], 0.f);
                    float r2 = fmaxf(acc[mi][ni][2], 0.f);
                    float r3 = fmaxf(acc[mi][ni][3], 0.f);
                    __half h0, l0, h1, l1, hh2, ll2, h3, l3;
                    split_hf(r0, h0, l0); split_hf(r1, h1, l1);
                    split_hf(r2, hh2, ll2); split_hf(r3, h3, l3);
                    ah2[mi][kc][2 * h2]     = pkhf(h0, h1);
                    ah2[mi][kc][2 * h2 + 1] = pkhf(hh2, h3);
                    al2[mi][kc][2 * h2]     = pkhf(l0, l1);
                    al2[mi][kc][2 * h2 + 1] = pkhf(ll2, l3);
                }

        // ---- layer 2 (A in registers) fused with W3 reduction ----
        float ws[4] = {0.f, 0.f, 0.f, 0.f};
#pragma unroll
        for (int np = 0; np < 4; np++) {
            float acc2[2][2][4];
#pragma unroll
            for (int mi = 0; mi < 2; mi++)
#pragma unroll
                for (int q = 0; q < 2; q++) {
                    const int ni = 2 * np + q;
                    acc2[mi][q][0] = b2v[2 * ni];
                    acc2[mi][q][1] = b2v[2 * ni + 1];
                    acc2[mi][q][2] = b2v[2 * ni];
                    acc2[mi][q][3] = b2v[2 * ni + 1];
                }
#pragma unroll
            for (int kc = 0; kc < 4; kc++) {
                uint32_t bh[4], bl[4];
                uint32_t off = roff(np * 16 + b_ro, 2 * kc + b_co);
                ldsm4(bh, sb + SM_W2H + off);
                ldsm4(bl, sb + SM_W2L + off);
#pragma unroll
                for (int mi = 0; mi < 2; mi++)
#pragma unroll
                    for (int q = 0; q < 2; q++) {
                        mma16816(acc2[mi][q], ah2[mi][kc], &bh[q * 2]);
                        mma16816(acc2[mi][q], al2[mi][kc], &bh[q * 2]);
                        mma16816(acc2[mi][q], ah2[mi][kc], &bl[q * 2]);
                    }
            }
#pragma unroll
            for (int mi = 0; mi < 2; mi++)
#pragma unroll
                for (int q = 0; q < 2; q++) {
                    const int ni = 2 * np + q;
                    ws[2 * mi]     = fmaf(w3v[2 * ni], fmaxf(acc2[mi][q][0], 0.f),
                                     fmaf(w3v[2 * ni + 1], fmaxf(acc2[mi][q][1], 0.f), ws[2 * mi]));
                    ws[2 * mi + 1] = fmaf(w3v[2 * ni], fmaxf(acc2[mi][q][2], 0.f),
                                     fmaf(w3v[2 * ni + 1], fmaxf(acc2[mi][q][3], 0.f), ws[2 * mi + 1]));
                }
        }

#pragma unroll
        for (int i = 0; i < 4; i++) {
            ws[i] += __shfl_xor_sync(0xffffffffu, ws[i], 1);
            ws[i] += __shfl_xor_sync(0xffffffffu, ws[i], 2);
        }
        float* wrowW = wrow + wid * 32;
        if ((lane & 3) == 0) {
            int r = lane >> 2;
            wrowW[r] = ws[0]; wrowW[r + 8] = ws[1];
            wrowW[r + 16] = ws[2]; wrowW[r + 24] = ws[3];
        }
        __syncwarp();

        // per-point finish
        float contrib = 0.f, mval = 0.f;
        {
            float w = wrowW[lane] + b3v;
            if (valid) {
                size_t gi = (size_t)t * NN + pg;
                float mf = (mask_kind == 0) ? (float)mask_raw[gi]
                         : (mask_kind == 1) ? (float)((const int*)mask_raw)[gi]
                         : ((const float*)mask_raw)[gi];
                float wm = w * mf;
                out_w[gi] = wm;
                contrib = wm * rets[gi];
                mval = mf;
            }
        }
#pragma unroll
        for (int off = 16; off; off >>= 1) {
            contrib += __shfl_down_sync(0xffffffffu, contrib, off);
            mval    += __shfl_down_sync(0xffffffffu, mval, off);
        }
        if (lane == 0) {
            atomicAdd(&g_sum[t], contrib);
            atomicAdd(&g_cnt[t], mval);
        }
    }
}

// ---------- K5: sdf finalize ----------
__global__ void __launch_bounds__(256) k_final(float* __restrict__ out_sdf) {
    __shared__ float smr[256];
    int t = threadIdx.x;
    float cnt = g_cnt[t];
    smr[t] = cnt;
    __syncthreads();
    for (int s = 128; s > 0; s >>= 1) {
        if (t < s) smr[t] += smr[t + s];
        __syncthreads();
    }
    float mean = smr[0] * (1.0f / 256.0f);
    out_sdf[t] = g_sum[t] / cnt * mean + 1.0f;
}

// ---------- launch ----------
extern "C" void kernel_launch(void* const* d_in, const int* in_sizes, int n_in,
                              void* d_out, int out_size) {
    (void)in_sizes; (void)n_in; (void)out_size;
    const float* macro = (const float*)d_in[0];
    const float* indiv = (const float*)d_in[1];
    const unsigned char* masks = (const unsigned char*)d_in[2];
    const float* rets  = (const float*)d_in[3];
    const float* W_ih  = (const float*)d_in[4];
    const float* W_hh  = (const float*)d_in[5];
    const float* b_ih  = (const float*)d_in[6];
    const float* b_hh  = (const float*)d_in[7];
    const float* W1    = (const float*)d_in[8];
    const float* b1    = (const float*)d_in[9];
    const float* W2    = (const float*)d_in[10];
    const float* b2    = (const float*)d_in[11];
    const float* W3    = (const float*)d_in[12];
    const float* b3    = (const float*)d_in[13];

    float* out     = (float*)d_out;
    float* out_sdf = out;          // sdf [T,1]
    float* out_w   = out + T_;     // weights [1,T,N,1]

    cudaFuncSetAttribute(k_prep, cudaFuncAttributeMaxDynamicSharedMemorySize, PREP_SMEM);
    cudaFuncSetAttribute(k_lstm, cudaFuncAttributeMaxDynamicSharedMemorySize, LSTM_SMEM);
    cudaFuncSetAttribute(k_mlp,  cudaFuncAttributeMaxDynamicSharedMemorySize, SMEM_MLP);

    // prep: plain launch (dependents wait for full completion)
    k_prep<<<64, 256, PREP_SMEM>>>(macro, W_ih, b_ih, b_hh, masks);

    // lstm: PDL-dependent on prep; triggers early so mlp overlaps the scan
    {
        cudaLaunchConfig_t cfg = {};
        cfg.gridDim = dim3(1, 1, 1);
        cfg.blockDim = dim3(256, 1, 1);
        cfg.dynamicSmemBytes = LSTM_SMEM;
        cudaLaunchAttribute at[1];
        at[0].id = cudaLaunchAttributeProgrammaticStreamSerialization;
        at[0].val.programmaticStreamSerializationAllowed = 1;
        cfg.attrs = at;
        cfg.numAttrs = 1;
        cudaLaunchKernelEx(&cfg, k_lstm, W_hh, W1, b1);
    }

    // mlp: PDL-dependent on lstm's early trigger; consumes macro1 via chunk flags
    {
        cudaLaunchConfig_t cfg = {};
        cfg.gridDim = dim3(GRID_MLP, 1, 1);
        cfg.blockDim = dim3(128, 1, 1);
        cfg.dynamicSmemBytes = SMEM_MLP;
        cudaLaunchAttribute at[1];
        at[0].id = cudaLaunchAttributeProgrammaticStreamSerialization;
        at[0].val.programmaticStreamSerializationAllowed = 1;
        cfg.attrs = at;
        cfg.numAttrs = 1;
        cudaLaunchKernelEx(&cfg, k_mlp, indiv, masks, rets, W1, W2, b2, W3, b3, out_w);
    }

    k_final<<<1, T_>>>(out_sdf);
}

// round 14
// speedup vs baseline: 1.0532x; 1.0532x over previous
#include <cuda_runtime.h>
#include <cuda_fp16.h>
#include <cstdint>

#define T_  256
#define NN  4000
#define DM  178
#define DI  46
#define H_  64
#define DH  64
#define FF  110   // DI + H
#define G4  256   // 4*H
#define TILE 128
#define NTILES (T_ * 32)   // 8192
#define GRID_MLP 296

typedef unsigned long long u64;

// ---------- device scratch ----------
__device__ float g_XZ[T_ * G4];
__device__ float g_macro1[T_ * DH];
__device__ float g_sum[T_];
__device__ float g_cnt[T_];
__device__ int   g_mask_kind;   // 0=uint8/bool, 1=int32, 2=float32
__device__ unsigned g_done;     // CTA completion ticket (reset by k_prep)

// ---------- packed f32x2 helpers ----------
__device__ __forceinline__ u64 pk2(float lo, float hi) {
    u64 r; asm("mov.b64 %0, {%1, %2};" : "=l"(r) : "f"(lo), "f"(hi)); return r;
}
__device__ __forceinline__ u64 ffma2(u64 a, u64 b, u64 c) {
    u64 d; asm("fma.rn.f32x2 %0, %1, %2, %3;" : "=l"(d) : "l"(a), "l"(b), "l"(c)); return d;
}
__device__ __forceinline__ float2 up2(u64 a) {
    float2 f; asm("mov.b64 {%0, %1}, %2;" : "=f"(f.x), "=f"(f.y) : "l"(a)); return f;
}

// ---------- activations ----------
__device__ __forceinline__ float sigm(float x) {
    float e = exp2f(-1.44269504088896340736f * x);
    return __fdividef(1.0f, 1.0f + e);
}
__device__ __forceinline__ float tanh_(float x) {
    float a = fabsf(x);
    float e = exp2f(-2.88539008177792681472f * a);
    float r = __fdividef(1.0f - e, 1.0f + e);
    return copysignf(r, x);
}

// ---------- warp MMA helpers ----------
__device__ __forceinline__ uint32_t smem_u32(const void* p) {
    uint32_t a;
    asm("{ .reg .u64 t; cvta.to.shared.u64 t, %1; cvt.u32.u64 %0, t; }" : "=r"(a) : "l"(p));
    return a;
}
__device__ __forceinline__ void ldsm4(uint32_t* r, uint32_t addr) {
    asm volatile("ldmatrix.sync.aligned.m8n8.x4.shared.b16 {%0,%1,%2,%3}, [%4];"
        : "=r"(r[0]), "=r"(r[1]), "=r"(r[2]), "=r"(r[3]) : "r"(addr));
}
__device__ __forceinline__ void mma16816(float* d, const uint32_t* a, const uint32_t* b) {
    asm volatile("mma.sync.aligned.m16n8k16.row.col.f32.f16.f16.f32 "
        "{%0,%1,%2,%3}, {%4,%5,%6,%7}, {%8,%9}, {%0,%1,%2,%3};"
        : "+f"(d[0]), "+f"(d[1]), "+f"(d[2]), "+f"(d[3])
        : "r"(a[0]), "r"(a[1]), "r"(a[2]), "r"(a[3]), "r"(b[0]), "r"(b[1]));
}
__device__ __forceinline__ uint32_t pkhf(__half a, __half b) {
    return ((uint32_t)__half_as_ushort(b) << 16) | (uint32_t)__half_as_ushort(a);
}
__device__ __forceinline__ void split_hf(float x, __half& h, __half& l) {
    h = __float2half_rn(x);
    l = __float2half_rn(x - __half2float(h));
}
// row/chunk -> byte offset: 144B row stride, chunk rotation mod 9
__device__ __forceinline__ uint32_t roff(int r, int c) {
    return (uint32_t)(r * 144 + ((c + (r >> 3)) % 9) * 16);
}
__device__ __forceinline__ void cp16(uint32_t saddr, const void* gaddr) {
    asm volatile("cp.async.cg.shared.global [%0], [%1], 16;" :: "r"(saddr), "l"(gaddr));
}

// ---------- K1: XZ with smem-cached W slice (64 blocks) + mask detect + resets ----------
#define PREP_SMEM ((64 * 185 + 16 * DM) * 4)
__global__ void __launch_bounds__(256) k_prep(const float* __restrict__ macro,
                                              const float* __restrict__ W_ih,
                                              const float* __restrict__ b_ih,
                                              const float* __restrict__ b_hh,
                                              const unsigned char* __restrict__ masks) {
    extern __shared__ float psm[];
    float* Wsm = psm;                 // [64][185]
    float* xs  = psm + 64 * 185;      // [16][178]
    const int tid = threadIdx.x;
    const int gg = blockIdx.x & 3, tg = blockIdx.x >> 2;

    for (int idx = tid; idx < 64 * DM; idx += 256) {
        int g = idx / DM, k = idx - g * DM;
        Wsm[g * 185 + k] = W_ih[(size_t)(gg * 64 + g) * DM + k];
    }
    for (int idx = tid; idx < 16 * DM; idx += 256) {
        int tt = idx / DM, k = idx - tt * DM;
        xs[tt * DM + k] = macro[(size_t)(tg * 16 + tt) * DM + k];
    }
    if (gg == 0 && tid < 16) {
        g_sum[tg * 16 + tid] = 0.f;
        g_cnt[tg * 16 + tid] = 0.f;
    }
    if (blockIdx.x == 1 && tid == 0) g_done = 0u;
    __syncthreads();

    const int g = tid & 63, tq = tid >> 6;
    const float bsum = b_ih[gg * 64 + g] + b_hh[gg * 64 + g];
    const float* wrow = Wsm + g * 185;
    for (int tt = tq; tt < 16; tt += 4) {
        const float* xr = xs + tt * DM;
        float a0 = 0.f, a1 = 0.f, a2 = 0.f, a3 = 0.f;
#pragma unroll 4
        for (int k = 0; k < 176; k += 4) {
            a0 = fmaf(wrow[k],     xr[k],     a0);
            a1 = fmaf(wrow[k + 1], xr[k + 1], a1);
            a2 = fmaf(wrow[k + 2], xr[k + 2], a2);
            a3 = fmaf(wrow[k + 3], xr[k + 3], a3);
        }
        a0 = fmaf(wrow[176], xr[176], a0);
        a1 = fmaf(wrow[177], xr[177], a1);
        g_XZ[(tg * 16 + tt) * G4 + gg * 64 + g] = ((a0 + a1) + (a2 + a3)) + bsum;
    }

    if (blockIdx.x == 0) {
        __shared__ int s_any, s_flt;
        if (tid == 0) { s_any = 0; s_flt = 0; }
        __syncthreads();
        int ta = 0, tf = 0;
        for (int j = tid; j < 1024; j += 256) {
            unsigned char c1 = masks[4 * j + 1], c2 = masks[4 * j + 2], c3 = masks[4 * j + 3];
            if (c1 | c2 | c3) ta = 1;
            if (c3 == 0x3F) tf = 1;
        }
        if (ta) atomicOr(&s_any, 1);
        if (tf) atomicOr(&s_flt, 1);
        __syncthreads();
        if (tid == 0) g_mask_kind = s_flt ? 2 : (s_any ? 0 : 1);
    }
}

// ---------- K2: LSTM scan (2 gates/thread, 1 shfl + 1 bar per step) + fused macro1 ----------
#define LSTM_SMEM ((T_ + 1) * H_ * 4)
__global__ void __launch_bounds__(256, 1) k_lstm(const float* __restrict__ W_hh,
                                                 const float* __restrict__ W1,
                                                 const float* __restrict__ b1) {
    extern __shared__ float hs[];
    const int tid = threadIdx.x;
    const int lane = tid & 31;
    const bool active = tid < 128;
    const bool roleA = (lane < 16);
    const int u = (tid >> 5) * 16 + (lane & 15);
    const int r0 = roleA ? u : (64 + u);            // i : f
    const int r1 = roleA ? (128 + u) : (192 + u);   // g : o

    u64 w0[32], w1[32];
    if (active) {
        const float4* A = (const float4*)(W_hh + (size_t)r0 * H_);
        const float4* B = (const float4*)(W_hh + (size_t)r1 * H_);
#pragma unroll
        for (int k = 0; k < 16; k++) {
            float4 va = A[k], vb = B[k];
            w0[2 * k] = pk2(va.x, va.y); w0[2 * k + 1] = pk2(va.z, va.w);
            w1[2 * k] = pk2(vb.x, vb.y); w1[2 * k + 1] = pk2(vb.z, vb.w);
        }
    }
    if (tid < H_) hs[tid] = 0.f;
    float c = 0.f;
    float z0 = active ? g_XZ[r0] : 0.f;
    float z1 = active ? g_XZ[r1] : 0.f;
    __syncthreads();

    const u64 one = pk2(1.f, 1.f);
    for (int t = 0; t < T_; t++) {
        if (active) {
            const u64* h64 = (const u64*)(hs + t * H_);
            u64 a0 = pk2(0.f, 0.f), a1 = a0, b0 = a0, b1a = a0;
#pragma unroll
            for (int k = 0; k < 32; k += 2) {
                a0  = ffma2(w0[k],     h64[k],     a0);
                a1  = ffma2(w0[k + 1], h64[k + 1], a1);
                b0  = ffma2(w1[k],     h64[k],     b0);
                b1a = ffma2(w1[k + 1], h64[k + 1], b1a);
            }
            a0 = ffma2(one, a1, a0);
            b0 = ffma2(one, b1a, b0);
            float2 sa = up2(a0), sb = up2(b0);
            float z0f = z0 + sa.x + sa.y;
            float z1f = z1 + sb.x + sb.y;
            if (t + 1 < T_) {
                z0 = g_XZ[(t + 1) * G4 + r0];
                z1 = g_XZ[(t + 1) * G4 + r1];
            }
            float p = 0.f;
            if (roleA) p = sigm(z0f) * tanh_(z1f);     // i*g
            p = __shfl_xor_sync(0xffffffffu, p, 16);
            if (!roleA) {
                float fv = sigm(z0f), ov = sigm(z1f);
                c = fmaf(fv, c, p);
                hs[(t + 1) * H_ + u] = ov * tanh_(c);
            }
        }
        __syncthreads();
    }

    // ---- fused macro1 (all 256 threads): m1[t][o] = b1[o] + W1[o][DI:] @ h_t ----
    const int o = tid & 63, tq = tid >> 6;
    u64 wm[32];
    {
        const float2* wr = (const float2*)(W1 + (size_t)o * FF + DI);
#pragma unroll
        for (int k = 0; k < 32; k++) { float2 v = wr[k]; wm[k] = pk2(v.x, v.y); }
    }
    const float b1v = b1[o];
    for (int t = tq; t < T_; t += 4) {
        const u64* h64 = (const u64*)(hs + (t + 1) * H_);
        u64 a0 = pk2(0.f, 0.f), a1 = a0, a2 = a0, a3 = a0;
#pragma unroll
        for (int k = 0; k < 32; k += 4) {
            a0 = ffma2(wm[k],     h64[k],     a0);
            a1 = ffma2(wm[k + 1], h64[k + 1], a1);
            a2 = ffma2(wm[k + 2], h64[k + 2], a2);
            a3 = ffma2(wm[k + 3], h64[k + 3], a3);
        }
        a0 = ffma2(one, a1, a0);
        a2 = ffma2(one, a3, a2);
        float2 s0 = up2(a0), s2 = up2(a2);
        g_macro1[t * DH + o] = ((s0.x + s0.y) + (s2.x + s2.y)) + b1v;
    }
}

// ---------- K4: warp-MMA fused MLP + inlined sdf finalize ----------
#define SM_XHI 0
#define SM_XLO 18432
#define SM_W1H 36864
#define SM_W1L 46080
#define SM_W2H 55296
#define SM_W2L 64512
#define SM_RAW 73728      // 4 warp slabs x 5888B
#define SM_WROW (SM_RAW + 23552)
#define SMEM_MLP (SM_WROW + 512)

__device__ __forceinline__ void do_layer1(
    uint32_t sb, const float* iv, float acc[2][8][4],
    int wid, int a_ro, int a_co, int b_ro, int b_co)
{
#pragma unroll
    for (int mi = 0; mi < 2; mi++)
#pragma unroll
        for (int ni = 0; ni < 8; ni++) {
            acc[mi][ni][0] = iv[2 * ni];
            acc[mi][ni][1] = iv[2 * ni + 1];
            acc[mi][ni][2] = iv[2 * ni];
            acc[mi][ni][3] = iv[2 * ni + 1];
        }
#pragma unroll
    for (int kc = 0; kc < 3; kc++) {
        uint32_t ah[2][4], al[2][4], bh[4][4], bl[4][4];
#pragma unroll
        for (int mi = 0; mi < 2; mi++) {
            uint32_t off = roff(wid * 32 + mi * 16 + a_ro, 2 * kc + a_co);
            ldsm4(ah[mi], sb + SM_XHI + off);
            ldsm4(al[mi], sb + SM_XLO + off);
        }
#pragma unroll
        for (int np = 0; np < 4; np++) {
            uint32_t off = roff(np * 16 + b_ro, 2 * kc + b_co);
            ldsm4(bh[np], sb + SM_W1H + off);
            ldsm4(bl[np], sb + SM_W1L + off);
        }
#pragma unroll
        for (int mi = 0; mi < 2; mi++)
#pragma unroll
            for (int ni = 0; ni < 8; ni++)
                mma16816(acc[mi][ni], ah[mi], &bh[ni >> 1][(ni & 1) * 2]);
#pragma unroll
        for (int mi = 0; mi < 2; mi++)
#pragma unroll
            for (int ni = 0; ni < 8; ni++)
                mma16816(acc[mi][ni], al[mi], &bh[ni >> 1][(ni & 1) * 2]);
#pragma unroll
        for (int mi = 0; mi < 2; mi++)
#pragma unroll
            for (int ni = 0; ni < 8; ni++)
                mma16816(acc[mi][ni], ah[mi], &bl[ni >> 1][(ni & 1) * 2]);
    }
}

__global__ void __launch_bounds__(128, 2)
k_mlp(const float* __restrict__ indiv, const unsigned char* __restrict__ mask_raw,
      const float* __restrict__ rets, const float* __restrict__ W1,
      const float* __restrict__ W2, const float* __restrict__ b2,
      const float* __restrict__ W3, const float* __restrict__ b3,
      float* __restrict__ out_w, float* __restrict__ out_sdf)
{
    extern __shared__ char sm[];
    const uint32_t sb = smem_u32(sm);
    float* wrow = (float*)(sm + SM_WROW);

    const int tid = threadIdx.x;
    const int wid = tid >> 5, lane = tid & 31;
    const int lq = lane & 7, qq = lane >> 3;
    const int a_ro = lq + ((qq & 1) << 3), a_co = qq >> 1;
    const int b_ro = lq + ((qq >> 1) << 3), b_co = qq & 1;
    const int cpair = (lane & 3) * 2;

    for (int idx = tid; idx < 64 * 64; idx += 128) {
        int n = idx >> 6, k = idx & 63;
        float v1 = (k < DI) ? W1[n * FF + k] : 0.f;
        float v2 = W2[idx];
        uint32_t o = roff(n, k >> 3) + (k & 7) * 2;
        __half h, l;
        split_hf(v1, h, l);
        *(__half*)(sm + SM_W1H + o) = h;
        *(__half*)(sm + SM_W1L + o) = l;
        split_hf(v2, h, l);
        *(__half*)(sm + SM_W2H + o) = h;
        *(__half*)(sm + SM_W2L + o) = l;
    }
    float b2v[16], w3v[16];
#pragma unroll
    for (int ni = 0; ni < 8; ni++) {
        b2v[2 * ni]     = b2[ni * 8 + cpair];
        b2v[2 * ni + 1] = b2[ni * 8 + cpair + 1];
        w3v[2 * ni]     = W3[ni * 8 + cpair];
        w3v[2 * ni + 1] = W3[ni * 8 + cpair + 1];
    }
    const float b3v = b3[0];
    const int mask_kind = g_mask_kind;
    __syncthreads();

    float acc[2][8][4];
    const uint32_t slab = sb + SM_RAW + wid * 5888;
    const float* rawf = (const float*)(sm + SM_RAW + wid * 5888);

    auto stage = [&](int tile) {
        const int t = tile >> 5;
        const int p0 = (tile & 31) * TILE;
        if ((p0 + wid * 32) < NN) {
            const float4* gsrc = (const float4*)(indiv + ((size_t)t * NN + p0 + wid * 32) * DI);
#pragma unroll
            for (int i = lane; i < 368; i += 32)
                cp16(slab + (uint32_t)i * 16, gsrc + i);
            asm volatile("cp.async.commit_group;" ::: "memory");
        }
    };

    if (blockIdx.x < NTILES) stage(blockIdx.x);

    for (int tile = blockIdx.x; tile < NTILES; tile += gridDim.x) {
        const int t = tile >> 5;
        const int p0 = (tile & 31) * TILE;
        const int pg = p0 + tid;
        const bool valid = pg < NN;

        float m1v[16];
#pragma unroll
        for (int ni = 0; ni < 8; ni++) {
            m1v[2 * ni]     = __ldg(&g_macro1[t * 64 + ni * 8 + cpair]);
            m1v[2 * ni + 1] = __ldg(&g_macro1[t * 64 + ni * 8 + cpair + 1]);
        }
        asm volatile("cp.async.wait_group 0;" ::: "memory");
        __syncwarp();

        // ---- split own row to fp16 hi/lo, swizzled STS (float2 raw reads) ----
        {
            const float2* rp2 = (const float2*)(rawf + lane * DI);
            const uint32_t rbase = (uint32_t)(tid * 144);
            const int rot0 = tid >> 3;
#pragma unroll
            for (int c = 0; c < 6; c++) {
                uint32_t hw[4], lw[4];
#pragma unroll
                for (int jp = 0; jp < 4; jp++) {
                    int pi = c * 4 + jp;
                    float2 v = (pi < 23) ? rp2[pi] : make_float2(0.f, 0.f);
                    if (!valid) v = make_float2(0.f, 0.f);
                    __half h0, l0, h1, l1;
                    split_hf(v.x, h0, l0);
                    split_hf(v.y, h1, l1);
                    hw[jp] = pkhf(h0, h1);
                    lw[jp] = pkhf(l0, l1);
                }
                uint32_t off = rbase + (uint32_t)(((c + rot0) % 9) * 16);
                *(uint4*)(sm + SM_XHI + off) = make_uint4(hw[0], hw[1], hw[2], hw[3]);
                *(uint4*)(sm + SM_XLO + off) = make_uint4(lw[0], lw[1], lw[2], lw[3]);
            }
        }
        __syncwarp();

        // ---- prefetch NEXT tile's X into the now-dead RAW slab (hides behind both layers) ----
        {
            int nxt = tile + gridDim.x;
            if (nxt < NTILES) stage(nxt);
        }

        // ---- layer 1: K=48 ----
        do_layer1(sb, m1v, acc, wid, a_ro, a_co, b_ro, b_co);

        // ---- C->A register identity: relu + split layer-1 acc into layer-2 A frags ----
        uint32_t ah2[2][4][4], al2[2][4][4];
#pragma unroll
        for (int mi = 0; mi < 2; mi++)
#pragma unroll
            for (int kc = 0; kc < 4; kc++)
#pragma unroll
                for (int h2 = 0; h2 < 2; h2++) {
                    const int ni = 2 * kc + h2;
                    float r0 = fmaxf(acc[mi][ni][0], 0.f);
                    float r1 = fmaxf(acc[mi][ni][1], 0.f);
                    float r2 = fmaxf(acc[mi][ni][2], 0.f);
                    float r3 = fmaxf(acc[mi][ni][3], 0.f);
                    __half h0, l0, h1, l1, hh2, ll2, h3, l3;
                    split_hf(r0, h0, l0); split_hf(r1, h1, l1);
                    split_hf(r2, hh2, ll2); split_hf(r3, h3, l3);
                    ah2[mi][kc][2 * h2]     = pkhf(h0, h1);
                    ah2[mi][kc][2 * h2 + 1] = pkhf(hh2, h3);
                    al2[mi][kc][2 * h2]     = pkhf(l0, l1);
                    al2[mi][kc][2 * h2 + 1] = pkhf(ll2, l3);
                }

        // ---- layer 2 (A in registers) fused with W3 reduction ----
        float ws[4] = {0.f, 0.f, 0.f, 0.f};
#pragma unroll
        for (int np = 0; np < 4; np++) {
            float acc2[2][2][4];
#pragma unroll
            for (int mi = 0; mi < 2; mi++)
#pragma unroll
                for (int q = 0; q < 2; q++) {
                    const int ni = 2 * np + q;
                    acc2[mi][q][0] = b2v[2 * ni];
                    acc2[mi][q][1] = b2v[2 * ni + 1];
                    acc2[mi][q][2] = b2v[2 * ni];
                    acc2[mi][q][3] = b2v[2 * ni + 1];
                }
#pragma unroll
            for (int kc = 0; kc < 4; kc++) {
                uint32_t bh[4], bl[4];
                uint32_t off = roff(np * 16 + b_ro, 2 * kc + b_co);
                ldsm4(bh, sb + SM_W2H + off);
                ldsm4(bl, sb + SM_W2L + off);
#pragma unroll
                for (int mi = 0; mi < 2; mi++)
#pragma unroll
                    for (int q = 0; q < 2; q++) {
                        mma16816(acc2[mi][q], ah2[mi][kc], &bh[q * 2]);
                        mma16816(acc2[mi][q], al2[mi][kc], &bh[q * 2]);
                        mma16816(acc2[mi][q], ah2[mi][kc], &bl[q * 2]);
                    }
            }
#pragma unroll
            for (int mi = 0; mi < 2; mi++)
#pragma unroll
                for (int q = 0; q < 2; q++) {
                    const int ni = 2 * np + q;
                    ws[2 * mi]     = fmaf(w3v[2 * ni], fmaxf(acc2[mi][q][0], 0.f),
                                     fmaf(w3v[2 * ni + 1], fmaxf(acc2[mi][q][1], 0.f), ws[2 * mi]));
                    ws[2 * mi + 1] = fmaf(w3v[2 * ni], fmaxf(acc2[mi][q][2], 0.f),
                                     fmaf(w3v[2 * ni + 1], fmaxf(acc2[mi][q][3], 0.f), ws[2 * mi + 1]));
                }
        }

#pragma unroll
        for (int i = 0; i < 4; i++) {
            ws[i] += __shfl_xor_sync(0xffffffffu, ws[i], 1);
            ws[i] += __shfl_xor_sync(0xffffffffu, ws[i], 2);
        }
        float* wrowW = wrow + wid * 32;
        if ((lane & 3) == 0) {
            int r = lane >> 2;
            wrowW[r] = ws[0]; wrowW[r + 8] = ws[1];
            wrowW[r + 16] = ws[2]; wrowW[r + 24] = ws[3];
        }
        __syncwarp();

        // per-point finish
        float contrib = 0.f, mval = 0.f;
        {
            float w = wrowW[lane] + b3v;
            if (valid) {
                size_t gi = (size_t)t * NN + pg;
                float mf = (mask_kind == 0) ? (float)mask_raw[gi]
                         : (mask_kind == 1) ? (float)((const int*)mask_raw)[gi]
                         : ((const float*)mask_raw)[gi];
                float wm = w * mf;
                out_w[gi] = wm;
                contrib = wm * rets[gi];
                mval = mf;
            }
        }
#pragma unroll
        for (int off = 16; off; off >>= 1) {
            contrib += __shfl_down_sync(0xffffffffu, contrib, off);
            mval    += __shfl_down_sync(0xffffffffu, mval, off);
        }
        if (lane == 0) {
            atomicAdd(&g_sum[t], contrib);
            atomicAdd(&g_cnt[t], mval);
        }
    }

    // ---- inlined finalize: last CTA computes sdf ----
    __shared__ unsigned s_last;
    __threadfence();   // make this CTA's g_sum/g_cnt atomics visible before ticket
    __syncthreads();
    if (tid == 0) s_last = (atomicAdd(&g_done, 1u) == (unsigned)(gridDim.x - 1));
    __syncthreads();
    if (s_last) {
        __threadfence();
        float* red = wrow;   // reuse 128-float scratch
        float csum = 0.f;
        float cnts[2], sums[2];
#pragma unroll
        for (int i = 0; i < 2; i++) {
            int t = tid + i * 128;
            cnts[i] = __ldcg(&g_cnt[t]);
            sums[i] = __ldcg(&g_sum[t]);
            csum += cnts[i];
        }
#pragma unroll
        for (int off = 16; off; off >>= 1)
            csum += __shfl_xor_sync(0xffffffffu, csum, off);
        if (lane == 0) red[wid] = csum;
        __syncthreads();
        float mean = (red[0] + red[1] + red[2] + red[3]) * (1.0f / 256.0f);
#pragma unroll
        for (int i = 0; i < 2; i++) {
            int t = tid + i * 128;
            out_sdf[t] = sums[i] / cnts[i] * mean + 1.0f;
        }
    }
}

// ---------- launch ----------
extern "C" void kernel_launch(void* const* d_in, const int* in_sizes, int n_in,
                              void* d_out, int out_size) {
    (void)in_sizes; (void)n_in; (void)out_size;
    const float* macro = (const float*)d_in[0];
    const float* indiv = (const float*)d_in[1];
    const unsigned char* masks = (const unsigned char*)d_in[2];
    const float* rets  = (const float*)d_in[3];
    const float* W_ih  = (const float*)d_in[4];
    const float* W_hh  = (const float*)d_in[5];
    const float* b_ih  = (const float*)d_in[6];
    const float* b_hh  = (const float*)d_in[7];
    const float* W1    = (const float*)d_in[8];
    const float* b1    = (const float*)d_in[9];
    const float* W2    = (const float*)d_in[10];
    const float* b2    = (const float*)d_in[11];
    const float* W3    = (const float*)d_in[12];
    const float* b3    = (const float*)d_in[13];

    float* out     = (float*)d_out;
    float* out_sdf = out;          // sdf [T,1]
    float* out_w   = out + T_;     // weights [1,T,N,1]

    cudaFuncSetAttribute(k_prep, cudaFuncAttributeMaxDynamicSharedMemorySize, PREP_SMEM);
    cudaFuncSetAttribute(k_lstm, cudaFuncAttributeMaxDynamicSharedMemorySize, LSTM_SMEM);
    cudaFuncSetAttribute(k_mlp,  cudaFuncAttributeMaxDynamicSharedMemorySize, SMEM_MLP);

    k_prep<<<64, 256, PREP_SMEM>>>(macro, W_ih, b_ih, b_hh, masks);
    k_lstm<<<1, 256, LSTM_SMEM>>>(W_hh, W1, b1);
    k_mlp<<<GRID_MLP, 128, SMEM_MLP>>>(indiv, masks, rets, W1, W2, b2, W3, b3,
                                       out_w, out_sdf);
}

// round 15
// speedup vs baseline: 1.0628x; 1.0091x over previous
#include <cuda_runtime.h>
#include <cuda_fp16.h>
#include <cstdint>

#define T_  256
#define NN  4000
#define DM  178
#define DI  46
#define H_  64
#define DH  64
#define FF  110   // DI + H
#define G4  256   // 4*H
#define TILE 128
#define NTILES (T_ * 32)   // 8192
#define GRID_MLP 296

typedef unsigned long long u64;

// ---------- device scratch ----------
__device__ float g_XZ[T_ * G4];
__device__ float g_macro1[T_ * DH];
__device__ float g_sum[T_];
__device__ float g_cnt[T_];
__device__ int   g_mask_kind;   // 0=uint8/bool, 1=int32, 2=float32
__device__ unsigned g_done;     // CTA completion ticket (reset by k_prep)

// ---------- packed f32x2 helpers ----------
__device__ __forceinline__ u64 pk2(float lo, float hi) {
    u64 r; asm("mov.b64 %0, {%1, %2};" : "=l"(r) : "f"(lo), "f"(hi)); return r;
}
__device__ __forceinline__ u64 ffma2(u64 a, u64 b, u64 c) {
    u64 d; asm("fma.rn.f32x2 %0, %1, %2, %3;" : "=l"(d) : "l"(a), "l"(b), "l"(c)); return d;
}
__device__ __forceinline__ float2 up2(u64 a) {
    float2 f; asm("mov.b64 {%0, %1}, %2;" : "=f"(f.x), "=f"(f.y) : "l"(a)); return f;
}

// ---------- activations ----------
__device__ __forceinline__ float sigm(float x) {
    float e = exp2f(-1.44269504088896340736f * x);
    return __fdividef(1.0f, 1.0f + e);
}
__device__ __forceinline__ float tanh_(float x) {
    float a = fabsf(x);
    float e = exp2f(-2.88539008177792681472f * a);
    float r = __fdividef(1.0f - e, 1.0f + e);
    return copysignf(r, x);
}

// ---------- warp MMA helpers ----------
__device__ __forceinline__ uint32_t smem_u32(const void* p) {
    uint32_t a;
    asm("{ .reg .u64 t; cvta.to.shared.u64 t, %1; cvt.u32.u64 %0, t; }" : "=r"(a) : "l"(p));
    return a;
}
__device__ __forceinline__ void ldsm4(uint32_t* r, uint32_t addr) {
    asm volatile("ldmatrix.sync.aligned.m8n8.x4.shared.b16 {%0,%1,%2,%3}, [%4];"
        : "=r"(r[0]), "=r"(r[1]), "=r"(r[2]), "=r"(r[3]) : "r"(addr));
}
__device__ __forceinline__ void mma16816(float* d, const uint32_t* a, const uint32_t* b) {
    asm volatile("mma.sync.aligned.m16n8k16.row.col.f32.f16.f16.f32 "
        "{%0,%1,%2,%3}, {%4,%5,%6,%7}, {%8,%9}, {%0,%1,%2,%3};"
        : "+f"(d[0]), "+f"(d[1]), "+f"(d[2]), "+f"(d[3])
        : "r"(a[0]), "r"(a[1]), "r"(a[2]), "r"(a[3]), "r"(b[0]), "r"(b[1]));
}
__device__ __forceinline__ uint32_t pkhf(__half a, __half b) {
    return ((uint32_t)__half_as_ushort(b) << 16) | (uint32_t)__half_as_ushort(a);
}
__device__ __forceinline__ void split_hf(float x, __half& h, __half& l) {
    h = __float2half_rn(x);
    l = __float2half_rn(x - __half2float(h));
}
// row/chunk -> byte offset: 144B row stride, chunk rotation mod 9
__device__ __forceinline__ uint32_t roff(int r, int c) {
    return (uint32_t)(r * 144 + ((c + (r >> 3)) % 9) * 16);
}
__device__ __forceinline__ void cp16(uint32_t saddr, const void* gaddr) {
    asm volatile("cp.async.cg.shared.global [%0], [%1], 16;" :: "r"(saddr), "l"(gaddr));
}

// ---------- K1: XZ with smem-cached W slice (256 blocks, 1 t/thread) ----------
#define PREP_SMEM ((64 * 185 + 4 * DM) * 4)
__global__ void __launch_bounds__(256) k_prep(const float* __restrict__ macro,
                                              const float* __restrict__ W_ih,
                                              const float* __restrict__ b_ih,
                                              const float* __restrict__ b_hh,
                                              const unsigned char* __restrict__ masks) {
    extern __shared__ float psm[];
    float* Wsm = psm;                 // [64][185]
    float* xs  = psm + 64 * 185;      // [4][178]
    const int tid = threadIdx.x;
    const int gg = blockIdx.x & 3, tg = blockIdx.x >> 2;   // tg 0..63

    for (int idx = tid; idx < 64 * DM; idx += 256) {
        int g = idx / DM, k = idx - g * DM;
        Wsm[g * 185 + k] = W_ih[(size_t)(gg * 64 + g) * DM + k];
    }
    for (int idx = tid; idx < 4 * DM; idx += 256) {
        int tt = idx / DM, k = idx - tt * DM;
        xs[tt * DM + k] = macro[(size_t)(tg * 4 + tt) * DM + k];
    }
    if (gg == 0 && tid < 4) {
        g_sum[tg * 4 + tid] = 0.f;
        g_cnt[tg * 4 + tid] = 0.f;
    }
    if (blockIdx.x == 1 && tid == 0) g_done = 0u;
    __syncthreads();

    const int g = tid & 63, tq = tid >> 6;   // one t per thread
    const float bsum = b_ih[gg * 64 + g] + b_hh[gg * 64 + g];
    const float* wrow = Wsm + g * 185;
    const float* xr = xs + tq * DM;
    float a0 = 0.f, a1 = 0.f, a2 = 0.f, a3 = 0.f;
#pragma unroll 4
    for (int k = 0; k < 176; k += 4) {
        a0 = fmaf(wrow[k],     xr[k],     a0);
        a1 = fmaf(wrow[k + 1], xr[k + 1], a1);
        a2 = fmaf(wrow[k + 2], xr[k + 2], a2);
        a3 = fmaf(wrow[k + 3], xr[k + 3], a3);
    }
    a0 = fmaf(wrow[176], xr[176], a0);
    a1 = fmaf(wrow[177], xr[177], a1);
    g_XZ[(tg * 4 + tq) * G4 + gg * 64 + g] = ((a0 + a1) + (a2 + a3)) + bsum;

    if (blockIdx.x == 0) {
        __shared__ int s_any, s_flt;
        if (tid == 0) { s_any = 0; s_flt = 0; }
        __syncthreads();
        int ta = 0, tf = 0;
        for (int j = tid; j < 1024; j += 256) {
            unsigned char c1 = masks[4 * j + 1], c2 = masks[4 * j + 2], c3 = masks[4 * j + 3];
            if (c1 | c2 | c3) ta = 1;
            if (c3 == 0x3F) tf = 1;
        }
        if (ta) atomicOr(&s_any, 1);
        if (tf) atomicOr(&s_flt, 1);
        __syncthreads();
        if (tid == 0) g_mask_kind = s_flt ? 2 : (s_any ? 0 : 1);
    }
}

// ---------- K2: LSTM scan (2 gates/thread, 1 shfl + 1 bar per step) + fused macro1 ----------
#define LSTM_SMEM ((T_ + 1) * H_ * 4)
__global__ void __launch_bounds__(256, 1) k_lstm(const float* __restrict__ W_hh,
                                                 const float* __restrict__ W1,
                                                 const float* __restrict__ b1) {
    extern __shared__ float hs[];
    const int tid = threadIdx.x;
    const int lane = tid & 31;
    const bool active = tid < 128;
    const bool roleA = (lane < 16);
    const int u = (tid >> 5) * 16 + (lane & 15);
    const int r0 = roleA ? u : (64 + u);            // i : f
    const int r1 = roleA ? (128 + u) : (192 + u);   // g : o

    u64 w0[32], w1[32];
    if (active) {
        const float4* A = (const float4*)(W_hh + (size_t)r0 * H_);
        const float4* B = (const float4*)(W_hh + (size_t)r1 * H_);
#pragma unroll
        for (int k = 0; k < 16; k++) {
            float4 va = A[k], vb = B[k];
            w0[2 * k] = pk2(va.x, va.y); w0[2 * k + 1] = pk2(va.z, va.w);
            w1[2 * k] = pk2(vb.x, vb.y); w1[2 * k + 1] = pk2(vb.z, vb.w);
        }
    }
    if (tid < H_) hs[tid] = 0.f;
    float c = 0.f;
    float z0 = active ? g_XZ[r0] : 0.f;
    float z1 = active ? g_XZ[r1] : 0.f;
    __syncthreads();

    const u64 one = pk2(1.f, 1.f);
    for (int t = 0; t < T_; t++) {
        if (active) {
            const u64* h64 = (const u64*)(hs + t * H_);
            u64 a0 = pk2(0.f, 0.f), a1 = a0, b0 = a0, b1a = a0;
#pragma unroll
            for (int k = 0; k < 32; k += 2) {
                a0  = ffma2(w0[k],     h64[k],     a0);
                a1  = ffma2(w0[k + 1], h64[k + 1], a1);
                b0  = ffma2(w1[k],     h64[k],     b0);
                b1a = ffma2(w1[k + 1], h64[k + 1], b1a);
            }
            a0 = ffma2(one, a1, a0);
            b0 = ffma2(one, b1a, b0);
            float2 sa = up2(a0), sb = up2(b0);
            float z0f = z0 + sa.x + sa.y;
            float z1f = z1 + sb.x + sb.y;
            if (t + 1 < T_) {
                z0 = g_XZ[(t + 1) * G4 + r0];
                z1 = g_XZ[(t + 1) * G4 + r1];
            }
            float p = 0.f;
            if (roleA) p = sigm(z0f) * tanh_(z1f);     // i*g
            p = __shfl_xor_sync(0xffffffffu, p, 16);
            if (!roleA) {
                float fv = sigm(z0f), ov = sigm(z1f);
                c = fmaf(fv, c, p);
                hs[(t + 1) * H_ + u] = ov * tanh_(c);
            }
        }
        __syncthreads();
    }

    // ---- fused macro1 (all 256 threads): m1[t][o] = b1[o] + W1[o][DI:] @ h_t ----
    const int o = tid & 63, tq = tid >> 6;
    u64 wm[32];
    {
        const float2* wr = (const float2*)(W1 + (size_t)o * FF + DI);
#pragma unroll
        for (int k = 0; k < 32; k++) { float2 v = wr[k]; wm[k] = pk2(v.x, v.y); }
    }
    const float b1v = b1[o];
    for (int t = tq; t < T_; t += 4) {
        const u64* h64 = (const u64*)(hs + (t + 1) * H_);
        u64 a0 = pk2(0.f, 0.f), a1 = a0, a2 = a0, a3 = a0;
#pragma unroll
        for (int k = 0; k < 32; k += 4) {
            a0 = ffma2(wm[k],     h64[k],     a0);
            a1 = ffma2(wm[k + 1], h64[k + 1], a1);
            a2 = ffma2(wm[k + 2], h64[k + 2], a2);
            a3 = ffma2(wm[k + 3], h64[k + 3], a3);
        }
        a0 = ffma2(one, a1, a0);
        a2 = ffma2(one, a3, a2);
        float2 s0 = up2(a0), s2 = up2(a2);
        g_macro1[t * DH + o] = ((s0.x + s0.y) + (s2.x + s2.y)) + b1v;
    }
}

// ---------- K4: warp-MMA fused MLP (8 warps x 16 rows) + inlined finalize ----------
#define SM_XHI 0
#define SM_XLO 18432
#define SM_W1H 36864
#define SM_W1L 46080
#define SM_W2H 55296
#define SM_W2L 64512
#define SM_RAW 73728      // 8 warp slabs x 2944B
#define SM_WROW (SM_RAW + 23552)
#define SMEM_MLP (SM_WROW + 512)

__global__ void __launch_bounds__(256, 2)
k_mlp(const float* __restrict__ indiv, const unsigned char* __restrict__ mask_raw,
      const float* __restrict__ rets, const float* __restrict__ W1,
      const float* __restrict__ W2, const float* __restrict__ b2,
      const float* __restrict__ W3, const float* __restrict__ b3,
      float* __restrict__ out_w, float* __restrict__ out_sdf)
{
    extern __shared__ char sm[];
    const uint32_t sb = smem_u32(sm);
    float* wrow = (float*)(sm + SM_WROW);

    const int tid = threadIdx.x;
    const int wid = tid >> 5, lane = tid & 31;
    const int lq = lane & 7, qq = lane >> 3;
    const int a_ro = lq + ((qq & 1) << 3), a_co = qq >> 1;
    const int b_ro = lq + ((qq >> 1) << 3), b_co = qq & 1;
    const int cpair = (lane & 3) * 2;

    for (int idx = tid; idx < 64 * 64; idx += 256) {
        int n = idx >> 6, k = idx & 63;
        float v1 = (k < DI) ? W1[n * FF + k] : 0.f;
        float v2 = W2[idx];
        uint32_t o = roff(n, k >> 3) + (k & 7) * 2;
        __half h, l;
        split_hf(v1, h, l);
        *(__half*)(sm + SM_W1H + o) = h;
        *(__half*)(sm + SM_W1L + o) = l;
        split_hf(v2, h, l);
        *(__half*)(sm + SM_W2H + o) = h;
        *(__half*)(sm + SM_W2L + o) = l;
    }
    float b2v[16], w3v[16], m1v[16];
#pragma unroll
    for (int ni = 0; ni < 8; ni++) {
        b2v[2 * ni]     = b2[ni * 8 + cpair];
        b2v[2 * ni + 1] = b2[ni * 8 + cpair + 1];
        w3v[2 * ni]     = W3[ni * 8 + cpair];
        w3v[2 * ni + 1] = W3[ni * 8 + cpair + 1];
    }
    const float b3v = b3[0];
    const int mask_kind = g_mask_kind;
    __syncthreads();

    float acc[8][4];
    const uint32_t slab = sb + SM_RAW + wid * 2944;
    const float* rawf = (const float*)(sm + SM_RAW + wid * 2944);

    auto stage = [&](int tile) {
        const int t = tile >> 5;
        const int p0 = (tile & 31) * TILE;
        if ((p0 + wid * 16) < NN) {
            const float4* gsrc = (const float4*)(indiv + ((size_t)t * NN + p0 + wid * 16) * DI);
#pragma unroll
            for (int i = lane; i < 184; i += 32)
                cp16(slab + (uint32_t)i * 16, gsrc + i);
            asm volatile("cp.async.commit_group;" ::: "memory");
        }
    };

    if (blockIdx.x < NTILES) stage(blockIdx.x);

    for (int tile = blockIdx.x; tile < NTILES; tile += gridDim.x) {
        const int t = tile >> 5;
        const int p0 = (tile & 31) * TILE;
        const bool wvalid = (p0 + wid * 16) < NN;   // 4000 % 16 == 0: row-uniform

#pragma unroll
        for (int ni = 0; ni < 8; ni++) {
            m1v[2 * ni]     = __ldg(&g_macro1[t * 64 + ni * 8 + cpair]);
            m1v[2 * ni + 1] = __ldg(&g_macro1[t * 64 + ni * 8 + cpair + 1]);
        }
        asm volatile("cp.async.wait_group 0;" ::: "memory");
        __syncwarp();

        // ---- split own half-row to fp16 hi/lo, swizzled STS ----
        {
            const int rw = lane >> 1;            // row within warp 0..15
            const int half = lane & 1;           // chunk half
            const int r = wid * 16 + rw;         // global tile row
            const float2* rp2 = (const float2*)(rawf + rw * DI);
            const uint32_t rbase = (uint32_t)(r * 144);
            const int rot0 = r >> 3;
#pragma unroll
            for (int ci = 0; ci < 3; ci++) {
                const int c = half * 3 + ci;
                uint32_t hw[4], lw[4];
#pragma unroll
                for (int jp = 0; jp < 4; jp++) {
                    int pi = c * 4 + jp;
                    float2 v = (wvalid && pi < 23) ? rp2[pi] : make_float2(0.f, 0.f);
                    __half h0, l0, h1, l1;
                    split_hf(v.x, h0, l0);
                    split_hf(v.y, h1, l1);
                    hw[jp] = pkhf(h0, h1);
                    lw[jp] = pkhf(l0, l1);
                }
                uint32_t off = rbase + (uint32_t)(((c + rot0) % 9) * 16);
                *(uint4*)(sm + SM_XHI + off) = make_uint4(hw[0], hw[1], hw[2], hw[3]);
                *(uint4*)(sm + SM_XLO + off) = make_uint4(lw[0], lw[1], lw[2], lw[3]);
            }
        }
        __syncwarp();

        // ---- prefetch NEXT tile's X into the now-dead RAW slab ----
        {
            int nxt = tile + gridDim.x;
            if (nxt < NTILES) stage(nxt);
        }

        // ---- layer 1: K=48 (A rows = warp's 16) ----
#pragma unroll
        for (int ni = 0; ni < 8; ni++) {
            acc[ni][0] = m1v[2 * ni];
            acc[ni][1] = m1v[2 * ni + 1];
            acc[ni][2] = m1v[2 * ni];
            acc[ni][3] = m1v[2 * ni + 1];
        }
#pragma unroll
        for (int kc = 0; kc < 3; kc++) {
            uint32_t ah[4], al[4], bh[4][4], bl[4][4];
            uint32_t aoff = roff(wid * 16 + a_ro, 2 * kc + a_co);
            ldsm4(ah, sb + SM_XHI + aoff);
            ldsm4(al, sb + SM_XLO + aoff);
#pragma unroll
            for (int np = 0; np < 4; np++) {
                uint32_t off = roff(np * 16 + b_ro, 2 * kc + b_co);
                ldsm4(bh[np], sb + SM_W1H + off);
                ldsm4(bl[np], sb + SM_W1L + off);
            }
#pragma unroll
            for (int ni = 0; ni < 8; ni++)
                mma16816(acc[ni], ah, &bh[ni >> 1][(ni & 1) * 2]);
#pragma unroll
            for (int ni = 0; ni < 8; ni++)
                mma16816(acc[ni], al, &bh[ni >> 1][(ni & 1) * 2]);
#pragma unroll
            for (int ni = 0; ni < 8; ni++)
                mma16816(acc[ni], ah, &bl[ni >> 1][(ni & 1) * 2]);
        }

        // ---- C->A register identity: relu + split into layer-2 A frags ----
        uint32_t ah2[4][4], al2[4][4];
#pragma unroll
        for (int kc = 0; kc < 4; kc++)
#pragma unroll
            for (int h2 = 0; h2 < 2; h2++) {
                const int ni = 2 * kc + h2;
                float r0 = fmaxf(acc[ni][0], 0.f);
                float r1 = fmaxf(acc[ni][1], 0.f);
                float r2 = fmaxf(acc[ni][2], 0.f);
                float r3 = fmaxf(acc[ni][3], 0.f);
                __half h0, l0, h1, l1, hh2, ll2, h3, l3;
                split_hf(r0, h0, l0); split_hf(r1, h1, l1);
                split_hf(r2, hh2, ll2); split_hf(r3, h3, l3);
                ah2[kc][2 * h2]     = pkhf(h0, h1);
                ah2[kc][2 * h2 + 1] = pkhf(hh2, h3);
                al2[kc][2 * h2]     = pkhf(l0, l1);
                al2[kc][2 * h2 + 1] = pkhf(ll2, l3);
            }

        // ---- layer 2 (A in registers) fused with W3 reduction ----
        float ws[2] = {0.f, 0.f};
#pragma unroll
        for (int np = 0; np < 4; np++) {
            float acc2[2][4];
#pragma unroll
            for (int q = 0; q < 2; q++) {
                const int ni = 2 * np + q;
                acc2[q][0] = b2v[2 * ni];
                acc2[q][1] = b2v[2 * ni + 1];
                acc2[q][2] = b2v[2 * ni];
                acc2[q][3] = b2v[2 * ni + 1];
            }
#pragma unroll
            for (int kc = 0; kc < 4; kc++) {
                uint32_t bh[4], bl[4];
                uint32_t off = roff(np * 16 + b_ro, 2 * kc + b_co);
                ldsm4(bh, sb + SM_W2H + off);
                ldsm4(bl, sb + SM_W2L + off);
#pragma unroll
                for (int q = 0; q < 2; q++) {
                    mma16816(acc2[q], ah2[kc], &bh[q * 2]);
                    mma16816(acc2[q], al2[kc], &bh[q * 2]);
                    mma16816(acc2[q], ah2[kc], &bl[q * 2]);
                }
            }
#pragma unroll
            for (int q = 0; q < 2; q++) {
                const int ni = 2 * np + q;
                ws[0] = fmaf(w3v[2 * ni], fmaxf(acc2[q][0], 0.f),
                        fmaf(w3v[2 * ni + 1], fmaxf(acc2[q][1], 0.f), ws[0]));
                ws[1] = fmaf(w3v[2 * ni], fmaxf(acc2[q][2], 0.f),
                        fmaf(w3v[2 * ni + 1], fmaxf(acc2[q][3], 0.f), ws[1]));
            }
        }

#pragma unroll
        for (int i = 0; i < 2; i++) {
            ws[i] += __shfl_xor_sync(0xffffffffu, ws[i], 1);
            ws[i] += __shfl_xor_sync(0xffffffffu, ws[i], 2);
        }
        float* wrowW = wrow + wid * 16;
        if ((lane & 3) == 0) {
            int r = lane >> 2;
            wrowW[r] = ws[0];
            wrowW[r + 8] = ws[1];
        }
        __syncwarp();

        // per-point finish (lanes 0-15, one point each)
        float contrib = 0.f, mval = 0.f;
        if (wvalid && lane < 16) {
            float w = wrowW[lane] + b3v;
            size_t gi = (size_t)t * NN + p0 + wid * 16 + lane;
            float mf = (mask_kind == 0) ? (float)mask_raw[gi]
                     : (mask_kind == 1) ? (float)((const int*)mask_raw)[gi]
                     : ((const float*)mask_raw)[gi];
            float wm = w * mf;
            out_w[gi] = wm;
            contrib = wm * rets[gi];
            mval = mf;
        }
#pragma unroll
        for (int off = 16; off; off >>= 1) {
            contrib += __shfl_down_sync(0xffffffffu, contrib, off);
            mval    += __shfl_down_sync(0xffffffffu, mval, off);
        }
        if (lane == 0 && wvalid) {
            atomicAdd(&g_sum[t], contrib);
            atomicAdd(&g_cnt[t], mval);
        }
    }

    // ---- inlined finalize: last CTA computes sdf (256 threads = 256 t's) ----
    __shared__ unsigned s_last;
    __threadfence();
    __syncthreads();
    if (tid == 0) s_last = (atomicAdd(&g_done, 1u) == (unsigned)(gridDim.x - 1));
    __syncthreads();
    if (s_last) {
        __threadfence();
        float* red = wrow;   // reuse scratch
        float cnt = __ldcg(&g_cnt[tid]);
        float sum = __ldcg(&g_sum[tid]);
        float csum = cnt;
#pragma unroll
        for (int off = 16; off; off >>= 1)
            csum += __shfl_xor_sync(0xffffffffu, csum, off);
        if (lane == 0) red[wid] = csum;
        __syncthreads();
        float mean = (((red[0] + red[1]) + (red[2] + red[3])) +
                      ((red[4] + red[5]) + (red[6] + red[7]))) * (1.0f / 256.0f);
        out_sdf[tid] = sum / cnt * mean + 1.0f;
    }
}

// ---------- launch ----------
extern "C" void kernel_launch(void* const* d_in, const int* in_sizes, int n_in,
                              void* d_out, int out_size) {
    (void)in_sizes; (void)n_in; (void)out_size;
    const float* macro = (const float*)d_in[0];
    const float* indiv = (const float*)d_in[1];
    const unsigned char* masks = (const unsigned char*)d_in[2];
    const float* rets  = (const float*)d_in[3];
    const float* W_ih  = (const float*)d_in[4];
    const float* W_hh  = (const float*)d_in[5];
    const float* b_ih  = (const float*)d_in[6];
    const float* b_hh  = (const float*)d_in[7];
    const float* W1    = (const float*)d_in[8];
    const float* b1    = (const float*)d_in[9];
    const float* W2    = (const float*)d_in[10];
    const float* b2    = (const float*)d_in[11];
    const float* W3    = (const float*)d_in[12];
    const float* b3    = (const float*)d_in[13];

    float* out     = (float*)d_out;
    float* out_sdf = out;          // sdf [T,1]
    float* out_w   = out + T_;     // weights [1,T,N,1]

    cudaFuncSetAttribute(k_prep, cudaFuncAttributeMaxDynamicSharedMemorySize, PREP_SMEM);
    cudaFuncSetAttribute(k_lstm, cudaFuncAttributeMaxDynamicSharedMemorySize, LSTM_SMEM);
    cudaFuncSetAttribute(k_mlp,  cudaFuncAttributeMaxDynamicSharedMemorySize, SMEM_MLP);

    k_prep<<<256, 256, PREP_SMEM>>>(macro, W_ih, b_ih, b_hh, masks);
    k_lstm<<<1, 256, LSTM_SMEM>>>(W_hh, W1, b1);
    k_mlp<<<GRID_MLP, 256, SMEM_MLP>>>(indiv, masks, rets, W1, W2, b2, W3, b3,
                                       out_w, out_sdf);
}

// round 16
// speedup vs baseline: 1.0882x; 1.0239x over previous
#include <cuda_runtime.h>
#include <cuda_fp16.h>
#include <cstdint>

#define T_  256
#define NN  4000
#define DM  178
#define DI  46
#define H_  64
#define DH  64
#define FF  110   // DI + H
#define G4  256   // 4*H
#define TILE 128
#define NTILES (T_ * 32)   // 8192
#define GRID_MLP 296

typedef unsigned long long u64;

// ---------- device scratch ----------
__device__ float g_XZ[T_ * G4];
__device__ float g_macro1[T_ * DH];
__device__ float g_sum[T_];
__device__ float g_cnt[T_];
__device__ int   g_mask_kind;   // 0=uint8/bool, 1=int32, 2=float32
__device__ unsigned g_done;     // CTA completion ticket (reset by k_prep)

// ---------- packed f32x2 helpers ----------
__device__ __forceinline__ u64 pk2(float lo, float hi) {
    u64 r; asm("mov.b64 %0, {%1, %2};" : "=l"(r) : "f"(lo), "f"(hi)); return r;
}
__device__ __forceinline__ u64 ffma2(u64 a, u64 b, u64 c) {
    u64 d; asm("fma.rn.f32x2 %0, %1, %2, %3;" : "=l"(d) : "l"(a), "l"(b), "l"(c)); return d;
}
__device__ __forceinline__ float2 up2(u64 a) {
    float2 f; asm("mov.b64 {%0, %1}, %2;" : "=f"(f.x), "=f"(f.y) : "l"(a)); return f;
}

// ---------- activations ----------
__device__ __forceinline__ float sigm(float x) {
    float e = exp2f(-1.44269504088896340736f * x);
    return __fdividef(1.0f, 1.0f + e);
}
__device__ __forceinline__ float tanh_(float x) {
    float a = fabsf(x);
    float e = exp2f(-2.88539008177792681472f * a);
    float r = __fdividef(1.0f - e, 1.0f + e);
    return copysignf(r, x);
}

// ---------- warp MMA helpers ----------
__device__ __forceinline__ uint32_t smem_u32(const void* p) {
    uint32_t a;
    asm("{ .reg .u64 t; cvta.to.shared.u64 t, %1; cvt.u32.u64 %0, t; }" : "=r"(a) : "l"(p));
    return a;
}
__device__ __forceinline__ void ldsm4(uint32_t* r, uint32_t addr) {
    asm volatile("ldmatrix.sync.aligned.m8n8.x4.shared.b16 {%0,%1,%2,%3}, [%4];"
        : "=r"(r[0]), "=r"(r[1]), "=r"(r[2]), "=r"(r[3]) : "r"(addr));
}
__device__ __forceinline__ void mma16816(float* d, const uint32_t* a, const uint32_t* b) {
    asm volatile("mma.sync.aligned.m16n8k16.row.col.f32.f16.f16.f32 "
        "{%0,%1,%2,%3}, {%4,%5,%6,%7}, {%8,%9}, {%0,%1,%2,%3};"
        : "+f"(d[0]), "+f"(d[1]), "+f"(d[2]), "+f"(d[3])
        : "r"(a[0]), "r"(a[1]), "r"(a[2]), "r"(a[3]), "r"(b[0]), "r"(b[1]));
}
__device__ __forceinline__ uint32_t pkhf(__half a, __half b) {
    return ((uint32_t)__half_as_ushort(b) << 16) | (uint32_t)__half_as_ushort(a);
}
__device__ __forceinline__ void split_hf(float x, __half& h, __half& l) {
    h = __float2half_rn(x);
    l = __float2half_rn(x - __half2float(h));
}
// row/chunk -> byte offset: 144B row stride, chunk rotation mod 9
__device__ __forceinline__ uint32_t roff(int r, int c) {
    return (uint32_t)(r * 144 + ((c + (r >> 3)) % 9) * 16);
}
__device__ __forceinline__ void cp16(uint32_t saddr, const void* gaddr) {
    asm volatile("cp.async.cg.shared.global [%0], [%1], 16;" :: "r"(saddr), "l"(gaddr));
}

// ---------- K1: XZ with smem-cached W slice (256 blocks, 1 t/thread) ----------
#define PREP_SMEM ((64 * 185 + 4 * DM) * 4)
__global__ void __launch_bounds__(256) k_prep(const float* __restrict__ macro,
                                              const float* __restrict__ W_ih,
                                              const float* __restrict__ b_ih,
                                              const float* __restrict__ b_hh,
                                              const unsigned char* __restrict__ masks) {
    extern __shared__ float psm[];
    float* Wsm = psm;                 // [64][185]
    float* xs  = psm + 64 * 185;      // [4][178]
    const int tid = threadIdx.x;
    const int gg = blockIdx.x & 3, tg = blockIdx.x >> 2;   // tg 0..63

    for (int idx = tid; idx < 64 * DM; idx += 256) {
        int g = idx / DM, k = idx - g * DM;
        Wsm[g * 185 + k] = W_ih[(size_t)(gg * 64 + g) * DM + k];
    }
    for (int idx = tid; idx < 4 * DM; idx += 256) {
        int tt = idx / DM, k = idx - tt * DM;
        xs[tt * DM + k] = macro[(size_t)(tg * 4 + tt) * DM + k];
    }
    if (gg == 0 && tid < 4) {
        g_sum[tg * 4 + tid] = 0.f;
        g_cnt[tg * 4 + tid] = 0.f;
    }
    if (blockIdx.x == 1 && tid == 0) g_done = 0u;
    __syncthreads();

    const int g = tid & 63, tq = tid >> 6;   // one t per thread
    const float bsum = b_ih[gg * 64 + g] + b_hh[gg * 64 + g];
    const float* wrow = Wsm + g * 185;
    const float* xr = xs + tq * DM;
    float a0 = 0.f, a1 = 0.f, a2 = 0.f, a3 = 0.f;
#pragma unroll 4
    for (int k = 0; k < 176; k += 4) {
        a0 = fmaf(wrow[k],     xr[k],     a0);
        a1 = fmaf(wrow[k + 1], xr[k + 1], a1);
        a2 = fmaf(wrow[k + 2], xr[k + 2], a2);
        a3 = fmaf(wrow[k + 3], xr[k + 3], a3);
    }
    a0 = fmaf(wrow[176], xr[176], a0);
    a1 = fmaf(wrow[177], xr[177], a1);
    g_XZ[(tg * 4 + tq) * G4 + gg * 64 + g] = ((a0 + a1) + (a2 + a3)) + bsum;

    if (blockIdx.x == 0) {
        __shared__ int s_any, s_flt;
        if (tid == 0) { s_any = 0; s_flt = 0; }
        __syncthreads();
        int ta = 0, tf = 0;
        for (int j = tid; j < 1024; j += 256) {
            unsigned char c1 = masks[4 * j + 1], c2 = masks[4 * j + 2], c3 = masks[4 * j + 3];
            if (c1 | c2 | c3) ta = 1;
            if (c3 == 0x3F) tf = 1;
        }
        if (ta) atomicOr(&s_any, 1);
        if (tf) atomicOr(&s_flt, 1);
        __syncthreads();
        if (tid == 0) g_mask_kind = s_flt ? 2 : (s_any ? 0 : 1);
    }
}

// ---------- K2: LSTM scan (2 gates/thread, 1 shfl + 1 bar per step) + fused macro1 ----------
#define LSTM_SMEM ((T_ + 1) * H_ * 4)
__global__ void __launch_bounds__(256, 1) k_lstm(const float* __restrict__ W_hh,
                                                 const float* __restrict__ W1,
                                                 const float* __restrict__ b1) {
    extern __shared__ float hs[];
    const int tid = threadIdx.x;
    const int lane = tid & 31;
    const bool active = tid < 128;
    const bool roleA = (lane < 16);
    const int u = (tid >> 5) * 16 + (lane & 15);
    const int r0 = roleA ? u : (64 + u);            // i : f
    const int r1 = roleA ? (128 + u) : (192 + u);   // g : o

    u64 w0[32], w1[32];
    if (active) {
        const float4* A = (const float4*)(W_hh + (size_t)r0 * H_);
        const float4* B = (const float4*)(W_hh + (size_t)r1 * H_);
#pragma unroll
        for (int k = 0; k < 16; k++) {
            float4 va = A[k], vb = B[k];
            w0[2 * k] = pk2(va.x, va.y); w0[2 * k + 1] = pk2(va.z, va.w);
            w1[2 * k] = pk2(vb.x, vb.y); w1[2 * k + 1] = pk2(vb.z, vb.w);
        }
    }
    if (tid < H_) hs[tid] = 0.f;
    float c = 0.f;
    float z0 = active ? g_XZ[r0] : 0.f;
    float z1 = active ? g_XZ[r1] : 0.f;
    __syncthreads();

    const u64 one = pk2(1.f, 1.f);
    for (int t = 0; t < T_; t++) {
        if (active) {
            const u64* h64 = (const u64*)(hs + t * H_);
            u64 a0 = pk2(0.f, 0.f), a1 = a0, b0 = a0, b1a = a0;
#pragma unroll
            for (int k = 0; k < 32; k += 2) {
                a0  = ffma2(w0[k],     h64[k],     a0);
                a1  = ffma2(w0[k + 1], h64[k + 1], a1);
                b0  = ffma2(w1[k],     h64[k],     b0);
                b1a = ffma2(w1[k + 1], h64[k + 1], b1a);
            }
            a0 = ffma2(one, a1, a0);
            b0 = ffma2(one, b1a, b0);
            float2 sa = up2(a0), sb = up2(b0);
            float z0f = z0 + sa.x + sa.y;
            float z1f = z1 + sb.x + sb.y;
            if (t + 1 < T_) {
                z0 = g_XZ[(t + 1) * G4 + r0];
                z1 = g_XZ[(t + 1) * G4 + r1];
            }
            float p = 0.f;
            if (roleA) p = sigm(z0f) * tanh_(z1f);     // i*g
            p = __shfl_xor_sync(0xffffffffu, p, 16);
            if (!roleA) {
                float fv = sigm(z0f), ov = sigm(z1f);
                c = fmaf(fv, c, p);
                hs[(t + 1) * H_ + u] = ov * tanh_(c);
            }
        }
        __syncthreads();
    }

    // ---- fused macro1 (all 256 threads): m1[t][o] = b1[o] + W1[o][DI:] @ h_t ----
    const int o = tid & 63, tq = tid >> 6;
    u64 wm[32];
    {
        const float2* wr = (const float2*)(W1 + (size_t)o * FF + DI);
#pragma unroll
        for (int k = 0; k < 32; k++) { float2 v = wr[k]; wm[k] = pk2(v.x, v.y); }
    }
    const float b1v = b1[o];
    for (int t = tq; t < T_; t += 4) {
        const u64* h64 = (const u64*)(hs + (t + 1) * H_);
        u64 a0 = pk2(0.f, 0.f), a1 = a0, a2 = a0, a3 = a0;
#pragma unroll
        for (int k = 0; k < 32; k += 4) {
            a0 = ffma2(wm[k],     h64[k],     a0);
            a1 = ffma2(wm[k + 1], h64[k + 1], a1);
            a2 = ffma2(wm[k + 2], h64[k + 2], a2);
            a3 = ffma2(wm[k + 3], h64[k + 3], a3);
        }
        a0 = ffma2(one, a1, a0);
        a2 = ffma2(one, a3, a2);
        float2 s0 = up2(a0), s2 = up2(a2);
        g_macro1[t * DH + o] = ((s0.x + s0.y) + (s2.x + s2.y)) + b1v;
    }
}

// ---------- K4: warp-MMA fused MLP (8 warps x 16 rows; layer2 2-term) + finalize ----------
#define SM_XHI 0
#define SM_XLO 18432
#define SM_W1H 36864
#define SM_W1L 46080
#define SM_W2H 55296
#define SM_W2L 64512
#define SM_RAW 73728      // 8 warp slabs x 2944B
#define SM_WROW (SM_RAW + 23552)
#define SMEM_MLP (SM_WROW + 512)

__global__ void __launch_bounds__(256, 2)
k_mlp(const float* __restrict__ indiv, const unsigned char* __restrict__ mask_raw,
      const float* __restrict__ rets, const float* __restrict__ W1,
      const float* __restrict__ W2, const float* __restrict__ b2,
      const float* __restrict__ W3, const float* __restrict__ b3,
      float* __restrict__ out_w, float* __restrict__ out_sdf)
{
    extern __shared__ char sm[];
    const uint32_t sb = smem_u32(sm);
    float* wrow = (float*)(sm + SM_WROW);

    const int tid = threadIdx.x;
    const int wid = tid >> 5, lane = tid & 31;
    const int lq = lane & 7, qq = lane >> 3;
    const int a_ro = lq + ((qq & 1) << 3), a_co = qq >> 1;
    const int b_ro = lq + ((qq >> 1) << 3), b_co = qq & 1;
    const int cpair = (lane & 3) * 2;

    for (int idx = tid; idx < 64 * 64; idx += 256) {
        int n = idx >> 6, k = idx & 63;
        float v1 = (k < DI) ? W1[n * FF + k] : 0.f;
        float v2 = W2[idx];
        uint32_t o = roff(n, k >> 3) + (k & 7) * 2;
        __half h, l;
        split_hf(v1, h, l);
        *(__half*)(sm + SM_W1H + o) = h;
        *(__half*)(sm + SM_W1L + o) = l;
        split_hf(v2, h, l);
        *(__half*)(sm + SM_W2H + o) = h;
        *(__half*)(sm + SM_W2L + o) = l;
    }
    float b2v[16], w3v[16], m1v[16];
#pragma unroll
    for (int ni = 0; ni < 8; ni++) {
        b2v[2 * ni]     = b2[ni * 8 + cpair];
        b2v[2 * ni + 1] = b2[ni * 8 + cpair + 1];
        w3v[2 * ni]     = W3[ni * 8 + cpair];
        w3v[2 * ni + 1] = W3[ni * 8 + cpair + 1];
    }
    const float b3v = b3[0];
    const int mask_kind = g_mask_kind;
    __syncthreads();

    float acc[8][4];
    const uint32_t slab = sb + SM_RAW + wid * 2944;
    const float* rawf = (const float*)(sm + SM_RAW + wid * 2944);

    auto stage = [&](int tile) {
        const int t = tile >> 5;
        const int p0 = (tile & 31) * TILE;
        if ((p0 + wid * 16) < NN) {
            const float4* gsrc = (const float4*)(indiv + ((size_t)t * NN + p0 + wid * 16) * DI);
#pragma unroll
            for (int i = lane; i < 184; i += 32)
                cp16(slab + (uint32_t)i * 16, gsrc + i);
            asm volatile("cp.async.commit_group;" ::: "memory");
        }
    };

    if (blockIdx.x < NTILES) stage(blockIdx.x);

    for (int tile = blockIdx.x; tile < NTILES; tile += gridDim.x) {
        const int t = tile >> 5;
        const int p0 = (tile & 31) * TILE;
        const bool wvalid = (p0 + wid * 16) < NN;   // 4000 % 16 == 0: row-uniform

#pragma unroll
        for (int ni = 0; ni < 8; ni++) {
            m1v[2 * ni]     = __ldg(&g_macro1[t * 64 + ni * 8 + cpair]);
            m1v[2 * ni + 1] = __ldg(&g_macro1[t * 64 + ni * 8 + cpair + 1]);
        }
        asm volatile("cp.async.wait_group 0;" ::: "memory");
        __syncwarp();

        // ---- split own half-row to fp16 hi/lo, swizzled STS ----
        {
            const int rw = lane >> 1;            // row within warp 0..15
            const int half = lane & 1;           // chunk half
            const int r = wid * 16 + rw;         // global tile row
            const float2* rp2 = (const float2*)(rawf + rw * DI);
            const uint32_t rbase = (uint32_t)(r * 144);
            const int rot0 = r >> 3;
#pragma unroll
            for (int ci = 0; ci < 3; ci++) {
                const int c = half * 3 + ci;
                uint32_t hw[4], lw[4];
#pragma unroll
                for (int jp = 0; jp < 4; jp++) {
                    int pi = c * 4 + jp;
                    float2 v = (wvalid && pi < 23) ? rp2[pi] : make_float2(0.f, 0.f);
                    __half h0, l0, h1, l1;
                    split_hf(v.x, h0, l0);
                    split_hf(v.y, h1, l1);
                    hw[jp] = pkhf(h0, h1);
                    lw[jp] = pkhf(l0, l1);
                }
                uint32_t off = rbase + (uint32_t)(((c + rot0) % 9) * 16);
                *(uint4*)(sm + SM_XHI + off) = make_uint4(hw[0], hw[1], hw[2], hw[3]);
                *(uint4*)(sm + SM_XLO + off) = make_uint4(lw[0], lw[1], lw[2], lw[3]);
            }
        }
        __syncwarp();

        // ---- prefetch NEXT tile's X into the now-dead RAW slab ----
        {
            int nxt = tile + gridDim.x;
            if (nxt < NTILES) stage(nxt);
        }

        // ---- layer 1: K=48, 3-term split ----
#pragma unroll
        for (int ni = 0; ni < 8; ni++) {
            acc[ni][0] = m1v[2 * ni];
            acc[ni][1] = m1v[2 * ni + 1];
            acc[ni][2] = m1v[2 * ni];
            acc[ni][3] = m1v[2 * ni + 1];
        }
#pragma unroll
        for (int kc = 0; kc < 3; kc++) {
            uint32_t ah[4], al[4], bh[4][4], bl[4][4];
            uint32_t aoff = roff(wid * 16 + a_ro, 2 * kc + a_co);
            ldsm4(ah, sb + SM_XHI + aoff);
            ldsm4(al, sb + SM_XLO + aoff);
#pragma unroll
            for (int np = 0; np < 4; np++) {
                uint32_t off = roff(np * 16 + b_ro, 2 * kc + b_co);
                ldsm4(bh[np], sb + SM_W1H + off);
                ldsm4(bl[np], sb + SM_W1L + off);
            }
#pragma unroll
            for (int ni = 0; ni < 8; ni++)
                mma16816(acc[ni], ah, &bh[ni >> 1][(ni & 1) * 2]);
#pragma unroll
            for (int ni = 0; ni < 8; ni++)
                mma16816(acc[ni], al, &bh[ni >> 1][(ni & 1) * 2]);
#pragma unroll
            for (int ni = 0; ni < 8; ni++)
                mma16816(acc[ni], ah, &bl[ni >> 1][(ni & 1) * 2]);
        }

        // ---- C->A register identity: relu + split into layer-2 A frags ----
        uint32_t ah2[4][4], al2[4][4];
#pragma unroll
        for (int kc = 0; kc < 4; kc++)
#pragma unroll
            for (int h2 = 0; h2 < 2; h2++) {
                const int ni = 2 * kc + h2;
                float r0 = fmaxf(acc[ni][0], 0.f);
                float r1 = fmaxf(acc[ni][1], 0.f);
                float r2 = fmaxf(acc[ni][2], 0.f);
                float r3 = fmaxf(acc[ni][3], 0.f);
                __half h0, l0, h1, l1, hh2, ll2, h3, l3;
                split_hf(r0, h0, l0); split_hf(r1, h1, l1);
                split_hf(r2, hh2, ll2); split_hf(r3, h3, l3);
                ah2[kc][2 * h2]     = pkhf(h0, h1);
                ah2[kc][2 * h2 + 1] = pkhf(hh2, h3);
                al2[kc][2 * h2]     = pkhf(l0, l1);
                al2[kc][2 * h2 + 1] = pkhf(ll2, l3);
            }

        // ---- layer 2: 2-term split (a1h*w2h + a1l*w2h), fused W3 reduction ----
        float ws[2] = {0.f, 0.f};
#pragma unroll
        for (int np = 0; np < 4; np++) {
            float acc2[2][4];
#pragma unroll
            for (int q = 0; q < 2; q++) {
                const int ni = 2 * np + q;
                acc2[q][0] = b2v[2 * ni];
                acc2[q][1] = b2v[2 * ni + 1];
                acc2[q][2] = b2v[2 * ni];
                acc2[q][3] = b2v[2 * ni + 1];
            }
#pragma unroll
            for (int kc = 0; kc < 4; kc++) {
                uint32_t bh[4];
                uint32_t off = roff(np * 16 + b_ro, 2 * kc + b_co);
                ldsm4(bh, sb + SM_W2H + off);
#pragma unroll
                for (int q = 0; q < 2; q++) {
                    mma16816(acc2[q], ah2[kc], &bh[q * 2]);
                    mma16816(acc2[q], al2[kc], &bh[q * 2]);
                }
            }
#pragma unroll
            for (int q = 0; q < 2; q++) {
                const int ni = 2 * np + q;
                ws[0] = fmaf(w3v[2 * ni], fmaxf(acc2[q][0], 0.f),
                        fmaf(w3v[2 * ni + 1], fmaxf(acc2[q][1], 0.f), ws[0]));
                ws[1] = fmaf(w3v[2 * ni], fmaxf(acc2[q][2], 0.f),
                        fmaf(w3v[2 * ni + 1], fmaxf(acc2[q][3], 0.f), ws[1]));
            }
        }

#pragma unroll
        for (int i = 0; i < 2; i++) {
            ws[i] += __shfl_xor_sync(0xffffffffu, ws[i], 1);
            ws[i] += __shfl_xor_sync(0xffffffffu, ws[i], 2);
        }
        float* wrowW = wrow + wid * 16;
        if ((lane & 3) == 0) {
            int r = lane >> 2;
            wrowW[r] = ws[0];
            wrowW[r + 8] = ws[1];
        }
        __syncwarp();

        // per-point finish (lanes 0-15, one point each)
        float contrib = 0.f, mval = 0.f;
        if (wvalid && lane < 16) {
            float w = wrowW[lane] + b3v;
            size_t gi = (size_t)t * NN + p0 + wid * 16 + lane;
            float mf = (mask_kind == 0) ? (float)mask_raw[gi]
                     : (mask_kind == 1) ? (float)((const int*)mask_raw)[gi]
                     : ((const float*)mask_raw)[gi];
            float wm = w * mf;
            out_w[gi] = wm;
            contrib = wm * rets[gi];
            mval = mf;
        }
#pragma unroll
        for (int off = 16; off; off >>= 1) {
            contrib += __shfl_down_sync(0xffffffffu, contrib, off);
            mval    += __shfl_down_sync(0xffffffffu, mval, off);
        }
        if (lane == 0 && wvalid) {
            atomicAdd(&g_sum[t], contrib);
            atomicAdd(&g_cnt[t], mval);
        }
    }

    // ---- inlined finalize: last CTA computes sdf (256 threads = 256 t's) ----
    __shared__ unsigned s_last;
    __threadfence();
    __syncthreads();
    if (tid == 0) s_last = (atomicAdd(&g_done, 1u) == (unsigned)(gridDim.x - 1));
    __syncthreads();
    if (s_last) {
        __threadfence();
        float* red = wrow;
        float cnt = __ldcg(&g_cnt[tid]);
        float sum = __ldcg(&g_sum[tid]);
        float csum = cnt;
#pragma unroll
        for (int off = 16; off; off >>= 1)
            csum += __shfl_xor_sync(0xffffffffu, csum, off);
        if (lane == 0) red[wid] = csum;
        __syncthreads();
        float mean = (((red[0] + red[1]) + (red[2] + red[3])) +
                      ((red[4] + red[5]) + (red[6] + red[7]))) * (1.0f / 256.0f);
        out_sdf[tid] = sum / cnt * mean + 1.0f;
    }
}

// ---------- launch ----------
extern "C" void kernel_launch(void* const* d_in, const int* in_sizes, int n_in,
                              void* d_out, int out_size) {
    (void)in_sizes; (void)n_in; (void)out_size;
    const float* macro = (const float*)d_in[0];
    const float* indiv = (const float*)d_in[1];
    const unsigned char* masks = (const unsigned char*)d_in[2];
    const float* rets  = (const float*)d_in[3];
    const float* W_ih  = (const float*)d_in[4];
    const float* W_hh  = (const float*)d_in[5];
    const float* b_ih  = (const float*)d_in[6];
    const float* b_hh  = (const float*)d_in[7];
    const float* W1    = (const float*)d_in[8];
    const float* b1    = (const float*)d_in[9];
    const float* W2    = (const float*)d_in[10];
    const float* b2    = (const float*)d_in[11];
    const float* W3    = (const float*)d_in[12];
    const float* b3    = (const float*)d_in[13];

    float* out     = (float*)d_out;
    float* out_sdf = out;          // sdf [T,1]
    float* out_w   = out + T_;     // weights [1,T,N,1]

    cudaFuncSetAttribute(k_prep, cudaFuncAttributeMaxDynamicSharedMemorySize, PREP_SMEM);
    cudaFuncSetAttribute(k_lstm, cudaFuncAttributeMaxDynamicSharedMemorySize, LSTM_SMEM);
    cudaFuncSetAttribute(k_mlp,  cudaFuncAttributeMaxDynamicSharedMemorySize, SMEM_MLP);

    k_prep<<<256, 256, PREP_SMEM>>>(macro, W_ih, b_ih, b_hh, masks);
    k_lstm<<<1, 256, LSTM_SMEM>>>(W_hh, W1, b1);
    k_mlp<<<GRID_MLP, 256, SMEM_MLP>>>(indiv, masks, rets, W1, W2, b2, W3, b3,
                                       out_w, out_sdf);
}

// round 17
// speedup vs baseline: 1.1818x; 1.0860x over previous
#include <cuda_runtime.h>
#include <cuda_fp16.h>
#include <cstdint>

#define T_  256
#define NN  4000
#define DM  178
#define DI  46
#define H_  64
#define DH  64
#define FF  110   // DI + H
#define G4  256   // 4*H
#define TILE 128
#define NTILES (T_ * 32)   // 8192
#define GRID_MLP 296

typedef unsigned long long u64;

// ---------- device scratch ----------
__device__ float g_XZ[T_ * G4];
__device__ float g_macro1[T_ * DH];
__device__ float g_sum[T_];
__device__ float g_cnt[T_];
__device__ int   g_mask_kind;   // 0=uint8/bool, 1=int32, 2=float32
__device__ unsigned g_done;     // CTA completion ticket (reset by k_prep)

// ---------- packed f32x2 helpers ----------
__device__ __forceinline__ u64 pk2(float lo, float hi) {
    u64 r; asm("mov.b64 %0, {%1, %2};" : "=l"(r) : "f"(lo), "f"(hi)); return r;
}
__device__ __forceinline__ u64 ffma2(u64 a, u64 b, u64 c) {
    u64 d; asm("fma.rn.f32x2 %0, %1, %2, %3;" : "=l"(d) : "l"(a), "l"(b), "l"(c)); return d;
}
__device__ __forceinline__ float2 up2(u64 a) {
    float2 f; asm("mov.b64 {%0, %1}, %2;" : "=f"(f.x), "=f"(f.y) : "l"(a)); return f;
}

// ---------- activations ----------
__device__ __forceinline__ float sigm(float x) {
    float e = exp2f(-1.44269504088896340736f * x);
    return __fdividef(1.0f, 1.0f + e);
}
__device__ __forceinline__ float tanh_(float x) {
    float a = fabsf(x);
    float e = exp2f(-2.88539008177792681472f * a);
    float r = __fdividef(1.0f - e, 1.0f + e);
    return copysignf(r, x);
}

// ---------- warp MMA helpers ----------
__device__ __forceinline__ uint32_t smem_u32(const void* p) {
    uint32_t a;
    asm("{ .reg .u64 t; cvta.to.shared.u64 t, %1; cvt.u32.u64 %0, t; }" : "=r"(a) : "l"(p));
    return a;
}
__device__ __forceinline__ void ldsm4(uint32_t* r, uint32_t addr) {
    asm volatile("ldmatrix.sync.aligned.m8n8.x4.shared.b16 {%0,%1,%2,%3}, [%4];"
        : "=r"(r[0]), "=r"(r[1]), "=r"(r[2]), "=r"(r[3]) : "r"(addr));
}
__device__ __forceinline__ void mma16816(float* d, const uint32_t* a, const uint32_t* b) {
    asm volatile("mma.sync.aligned.m16n8k16.row.col.f32.f16.f16.f32 "
        "{%0,%1,%2,%3}, {%4,%5,%6,%7}, {%8,%9}, {%0,%1,%2,%3};"
        : "+f"(d[0]), "+f"(d[1]), "+f"(d[2]), "+f"(d[3])
        : "r"(a[0]), "r"(a[1]), "r"(a[2]), "r"(a[3]), "r"(b[0]), "r"(b[1]));
}
__device__ __forceinline__ uint32_t pkhf(__half a, __half b) {
    return ((uint32_t)__half_as_ushort(b) << 16) | (uint32_t)__half_as_ushort(a);
}
__device__ __forceinline__ void split_hf(float x, __half& h, __half& l) {
    h = __float2half_rn(x);
    l = __float2half_rn(x - __half2float(h));
}
// row/chunk -> byte offset: 144B row stride, chunk rotation mod 9
__device__ __forceinline__ uint32_t roff(int r, int c) {
    return (uint32_t)(r * 144 + ((c + (r >> 3)) % 9) * 16);
}
__device__ __forceinline__ void cp16(uint32_t saddr, const void* gaddr) {
    asm volatile("cp.async.cg.shared.global [%0], [%1], 16;" :: "r"(saddr), "l"(gaddr));
}

// ---------- K1: XZ with smem-cached W slice (256 blocks, 1 t/thread) ----------
#define PREP_SMEM ((64 * 185 + 4 * DM) * 4)
__global__ void __launch_bounds__(256) k_prep(const float* __restrict__ macro,
                                              const float* __restrict__ W_ih,
                                              const float* __restrict__ b_ih,
                                              const float* __restrict__ b_hh,
                                              const unsigned char* __restrict__ masks) {
    extern __shared__ float psm[];
    float* Wsm = psm;                 // [64][185]
    float* xs  = psm + 64 * 185;      // [4][178]
    const int tid = threadIdx.x;
    const int gg = blockIdx.x & 3, tg = blockIdx.x >> 2;

    for (int idx = tid; idx < 64 * DM; idx += 256) {
        int g = idx / DM, k = idx - g * DM;
        Wsm[g * 185 + k] = W_ih[(size_t)(gg * 64 + g) * DM + k];
    }
    for (int idx = tid; idx < 4 * DM; idx += 256) {
        int tt = idx / DM, k = idx - tt * DM;
        xs[tt * DM + k] = macro[(size_t)(tg * 4 + tt) * DM + k];
    }
    if (gg == 0 && tid < 4) {
        g_sum[tg * 4 + tid] = 0.f;
        g_cnt[tg * 4 + tid] = 0.f;
    }
    if (blockIdx.x == 1 && tid == 0) g_done = 0u;
    __syncthreads();

    const int g = tid & 63, tq = tid >> 6;
    const float bsum = b_ih[gg * 64 + g] + b_hh[gg * 64 + g];
    const float* wrow = Wsm + g * 185;
    const float* xr = xs + tq * DM;
    float a0 = 0.f, a1 = 0.f, a2 = 0.f, a3 = 0.f;
#pragma unroll 4
    for (int k = 0; k < 176; k += 4) {
        a0 = fmaf(wrow[k],     xr[k],     a0);
        a1 = fmaf(wrow[k + 1], xr[k + 1], a1);
        a2 = fmaf(wrow[k + 2], xr[k + 2], a2);
        a3 = fmaf(wrow[k + 3], xr[k + 3], a3);
    }
    a0 = fmaf(wrow[176], xr[176], a0);
    a1 = fmaf(wrow[177], xr[177], a1);
    g_XZ[(tg * 4 + tq) * G4 + gg * 64 + g] = ((a0 + a1) + (a2 + a3)) + bsum;

    if (blockIdx.x == 0) {
        __shared__ int s_any, s_flt;
        if (tid == 0) { s_any = 0; s_flt = 0; }
        __syncthreads();
        int ta = 0, tf = 0;
        for (int j = tid; j < 1024; j += 256) {
            unsigned char c1 = masks[4 * j + 1], c2 = masks[4 * j + 2], c3 = masks[4 * j + 3];
            if (c1 | c2 | c3) ta = 1;
            if (c3 == 0x3F) tf = 1;
        }
        if (ta) atomicOr(&s_any, 1);
        if (tf) atomicOr(&s_flt, 1);
        __syncthreads();
        if (tid == 0) g_mask_kind = s_flt ? 2 : (s_any ? 0 : 1);
    }
}

// ---------- K2: LSTM scan (2 gates/thread, 1 shfl + 1 bar per step) + fused macro1 ----------
#define LSTM_SMEM ((T_ + 1) * H_ * 4)
__global__ void __launch_bounds__(256, 1) k_lstm(const float* __restrict__ W_hh,
                                                 const float* __restrict__ W1,
                                                 const float* __restrict__ b1) {
    extern __shared__ float hs[];
    const int tid = threadIdx.x;
    const int lane = tid & 31;
    const bool active = tid < 128;
    const bool roleA = (lane < 16);
    const int u = (tid >> 5) * 16 + (lane & 15);
    const int r0 = roleA ? u : (64 + u);            // i : f
    const int r1 = roleA ? (128 + u) : (192 + u);   // g : o

    u64 w0[32], w1[32];
    if (active) {
        const float4* A = (const float4*)(W_hh + (size_t)r0 * H_);
        const float4* B = (const float4*)(W_hh + (size_t)r1 * H_);
#pragma unroll
        for (int k = 0; k < 16; k++) {
            float4 va = A[k], vb = B[k];
            w0[2 * k] = pk2(va.x, va.y); w0[2 * k + 1] = pk2(va.z, va.w);
            w1[2 * k] = pk2(vb.x, vb.y); w1[2 * k + 1] = pk2(vb.z, vb.w);
        }
    }
    if (tid < H_) hs[tid] = 0.f;
    float c = 0.f;
    float z0 = active ? g_XZ[r0] : 0.f;
    float z1 = active ? g_XZ[r1] : 0.f;
    __syncthreads();

    const u64 one = pk2(1.f, 1.f);
    for (int t = 0; t < T_; t++) {
        if (active) {
            const u64* h64 = (const u64*)(hs + t * H_);
            u64 a0 = pk2(0.f, 0.f), a1 = a0, b0 = a0, b1a = a0;
#pragma unroll
            for (int k = 0; k < 32; k += 2) {
                a0  = ffma2(w0[k],     h64[k],     a0);
                a1  = ffma2(w0[k + 1], h64[k + 1], a1);
                b0  = ffma2(w1[k],     h64[k],     b0);
                b1a = ffma2(w1[k + 1], h64[k + 1], b1a);
            }
            a0 = ffma2(one, a1, a0);
            b0 = ffma2(one, b1a, b0);
            float2 sa = up2(a0), sb = up2(b0);
            float z0f = z0 + sa.x + sa.y;
            float z1f = z1 + sb.x + sb.y;
            if (t + 1 < T_) {
                z0 = g_XZ[(t + 1) * G4 + r0];
                z1 = g_XZ[(t + 1) * G4 + r1];
            }
            float p = 0.f;
            if (roleA) p = sigm(z0f) * tanh_(z1f);     // i*g
            p = __shfl_xor_sync(0xffffffffu, p, 16);
            if (!roleA) {
                float fv = sigm(z0f), ov = sigm(z1f);
                c = fmaf(fv, c, p);
                hs[(t + 1) * H_ + u] = ov * tanh_(c);
            }
        }
        __syncthreads();
    }

    // ---- fused macro1 (all 256 threads): m1[t][o] = b1[o] + W1[o][DI:] @ h_t ----
    const int o = tid & 63, tq = tid >> 6;
    u64 wm[32];
    {
        const float2* wr = (const float2*)(W1 + (size_t)o * FF + DI);
#pragma unroll
        for (int k = 0; k < 32; k++) { float2 v = wr[k]; wm[k] = pk2(v.x, v.y); }
    }
    const float b1v = b1[o];
    for (int t = tq; t < T_; t += 4) {
        const u64* h64 = (const u64*)(hs + (t + 1) * H_);
        u64 a0 = pk2(0.f, 0.f), a1 = a0, a2 = a0, a3 = a0;
#pragma unroll
        for (int k = 0; k < 32; k += 4) {
            a0 = ffma2(wm[k],     h64[k],     a0);
            a1 = ffma2(wm[k + 1], h64[k + 1], a1);
            a2 = ffma2(wm[k + 2], h64[k + 2], a2);
            a3 = ffma2(wm[k + 3], h64[k + 3], a3);
        }
        a0 = ffma2(one, a1, a0);
        a2 = ffma2(one, a3, a2);
        float2 s0 = up2(a0), s2 = up2(a2);
        g_macro1[t * DH + o] = ((s0.x + s0.y) + (s2.x + s2.y)) + b1v;
    }
}

// ---------- K4: warp-MMA fused MLP (8 warps x 16 rows; A-hi-only 2-term both layers) ----------
#define SM_XHI 0
#define SM_W1H 18432
#define SM_W1L 27648
#define SM_W2H 36864
#define SM_W2L 46080
#define SM_RAW 55296      // 8 warp slabs x 2944B
#define SM_WROW (SM_RAW + 23552)
#define SMEM_MLP (SM_WROW + 512)

__global__ void __launch_bounds__(256, 2)
k_mlp(const float* __restrict__ indiv, const unsigned char* __restrict__ mask_raw,
      const float* __restrict__ rets, const float* __restrict__ W1,
      const float* __restrict__ W2, const float* __restrict__ b2,
      const float* __restrict__ W3, const float* __restrict__ b3,
      float* __restrict__ out_w, float* __restrict__ out_sdf)
{
    extern __shared__ char sm[];
    const uint32_t sb = smem_u32(sm);
    float* wrow = (float*)(sm + SM_WROW);

    const int tid = threadIdx.x;
    const int wid = tid >> 5, lane = tid & 31;
    const int lq = lane & 7, qq = lane >> 3;
    const int a_ro = lq + ((qq & 1) << 3), a_co = qq >> 1;
    const int b_ro = lq + ((qq >> 1) << 3), b_co = qq & 1;
    const int cpair = (lane & 3) * 2;

    // weights staged hi/lo (both halves used as B operands now)
    for (int idx = tid; idx < 64 * 64; idx += 256) {
        int n = idx >> 6, k = idx & 63;
        float v1 = (k < DI) ? W1[n * FF + k] : 0.f;
        float v2 = W2[idx];
        uint32_t o = roff(n, k >> 3) + (k & 7) * 2;
        __half h, l;
        split_hf(v1, h, l);
        *(__half*)(sm + SM_W1H + o) = h;
        *(__half*)(sm + SM_W1L + o) = l;
        split_hf(v2, h, l);
        *(__half*)(sm + SM_W2H + o) = h;
        *(__half*)(sm + SM_W2L + o) = l;
    }
    float b2v[16], w3v[16], m1v[16];
#pragma unroll
    for (int ni = 0; ni < 8; ni++) {
        b2v[2 * ni]     = b2[ni * 8 + cpair];
        b2v[2 * ni + 1] = b2[ni * 8 + cpair + 1];
        w3v[2 * ni]     = W3[ni * 8 + cpair];
        w3v[2 * ni + 1] = W3[ni * 8 + cpair + 1];
    }
    const float b3v = b3[0];
    const int mask_kind = g_mask_kind;
    __syncthreads();

    float acc[8][4];
    const uint32_t slab = sb + SM_RAW + wid * 2944;
    const float* rawf = (const float*)(sm + SM_RAW + wid * 2944);

    auto stage = [&](int tile) {
        const int t = tile >> 5;
        const int p0 = (tile & 31) * TILE;
        if ((p0 + wid * 16) < NN) {
            const float4* gsrc = (const float4*)(indiv + ((size_t)t * NN + p0 + wid * 16) * DI);
#pragma unroll
            for (int i = lane; i < 184; i += 32)
                cp16(slab + (uint32_t)i * 16, gsrc + i);
            asm volatile("cp.async.commit_group;" ::: "memory");
        }
    };

    if (blockIdx.x < NTILES) stage(blockIdx.x);

    for (int tile = blockIdx.x; tile < NTILES; tile += gridDim.x) {
        const int t = tile >> 5;
        const int p0 = (tile & 31) * TILE;
        const bool wvalid = (p0 + wid * 16) < NN;

#pragma unroll
        for (int ni = 0; ni < 8; ni++) {
            m1v[2 * ni]     = __ldg(&g_macro1[t * 64 + ni * 8 + cpair]);
            m1v[2 * ni + 1] = __ldg(&g_macro1[t * 64 + ni * 8 + cpair + 1]);
        }
        asm volatile("cp.async.wait_group 0;" ::: "memory");
        __syncwarp();

        // ---- convert own half-row to fp16 hi ONLY, swizzled STS ----
        {
            const int rw = lane >> 1;
            const int half = lane & 1;
            const int r = wid * 16 + rw;
            const float2* rp2 = (const float2*)(rawf + rw * DI);
            const uint32_t rbase = (uint32_t)(r * 144);
            const int rot0 = r >> 3;
#pragma unroll
            for (int ci = 0; ci < 3; ci++) {
                const int c = half * 3 + ci;
                uint32_t hw[4];
#pragma unroll
                for (int jp = 0; jp < 4; jp++) {
                    int pi = c * 4 + jp;
                    float2 v = (wvalid && pi < 23) ? rp2[pi] : make_float2(0.f, 0.f);
                    hw[jp] = pkhf(__float2half_rn(v.x), __float2half_rn(v.y));
                }
                uint32_t off = rbase + (uint32_t)(((c + rot0) % 9) * 16);
                *(uint4*)(sm + SM_XHI + off) = make_uint4(hw[0], hw[1], hw[2], hw[3]);
            }
        }
        __syncwarp();

        // ---- prefetch NEXT tile's X into the now-dead RAW slab ----
        {
            int nxt = tile + gridDim.x;
            if (nxt < NTILES) stage(nxt);
        }

        // ---- layer 1: K=48, xh*(w1h + w1l) ----
#pragma unroll
        for (int ni = 0; ni < 8; ni++) {
            acc[ni][0] = m1v[2 * ni];
            acc[ni][1] = m1v[2 * ni + 1];
            acc[ni][2] = m1v[2 * ni];
            acc[ni][3] = m1v[2 * ni + 1];
        }
#pragma unroll
        for (int kc = 0; kc < 3; kc++) {
            uint32_t ah[4], bh[4][4], bl[4][4];
            uint32_t aoff = roff(wid * 16 + a_ro, 2 * kc + a_co);
            ldsm4(ah, sb + SM_XHI + aoff);
#pragma unroll
            for (int np = 0; np < 4; np++) {
                uint32_t off = roff(np * 16 + b_ro, 2 * kc + b_co);
                ldsm4(bh[np], sb + SM_W1H + off);
                ldsm4(bl[np], sb + SM_W1L + off);
            }
#pragma unroll
            for (int ni = 0; ni < 8; ni++)
                mma16816(acc[ni], ah, &bh[ni >> 1][(ni & 1) * 2]);
#pragma unroll
            for (int ni = 0; ni < 8; ni++)
                mma16816(acc[ni], ah, &bl[ni >> 1][(ni & 1) * 2]);
        }

        // ---- C->A register identity: relu + hi-convert into layer-2 A frags ----
        uint32_t ah2[4][4];
#pragma unroll
        for (int kc = 0; kc < 4; kc++)
#pragma unroll
            for (int h2 = 0; h2 < 2; h2++) {
                const int ni = 2 * kc + h2;
                float r0 = fmaxf(acc[ni][0], 0.f);
                float r1 = fmaxf(acc[ni][1], 0.f);
                float r2 = fmaxf(acc[ni][2], 0.f);
                float r3 = fmaxf(acc[ni][3], 0.f);
                ah2[kc][2 * h2]     = pkhf(__float2half_rn(r0), __float2half_rn(r1));
                ah2[kc][2 * h2 + 1] = pkhf(__float2half_rn(r2), __float2half_rn(r3));
            }

        // ---- layer 2: ah*(w2h + w2l), fused W3 reduction ----
        float ws[2] = {0.f, 0.f};
#pragma unroll
        for (int np = 0; np < 4; np++) {
            float acc2[2][4];
#pragma unroll
            for (int q = 0; q < 2; q++) {
                const int ni = 2 * np + q;
                acc2[q][0] = b2v[2 * ni];
                acc2[q][1] = b2v[2 * ni + 1];
                acc2[q][2] = b2v[2 * ni];
                acc2[q][3] = b2v[2 * ni + 1];
            }
#pragma unroll
            for (int kc = 0; kc < 4; kc++) {
                uint32_t bh[4], bl[4];
                uint32_t off = roff(np * 16 + b_ro, 2 * kc + b_co);
                ldsm4(bh, sb + SM_W2H + off);
                ldsm4(bl, sb + SM_W2L + off);
#pragma unroll
                for (int q = 0; q < 2; q++) {
                    mma16816(acc2[q], ah2[kc], &bh[q * 2]);
                    mma16816(acc2[q], ah2[kc], &bl[q * 2]);
                }
            }
#pragma unroll
            for (int q = 0; q < 2; q++) {
                const int ni = 2 * np + q;
                ws[0] = fmaf(w3v[2 * ni], fmaxf(acc2[q][0], 0.f),
                        fmaf(w3v[2 * ni + 1], fmaxf(acc2[q][1], 0.f), ws[0]));
                ws[1] = fmaf(w3v[2 * ni], fmaxf(acc2[q][2], 0.f),
                        fmaf(w3v[2 * ni + 1], fmaxf(acc2[q][3], 0.f), ws[1]));
            }
        }

#pragma unroll
        for (int i = 0; i < 2; i++) {
            ws[i] += __shfl_xor_sync(0xffffffffu, ws[i], 1);
            ws[i] += __shfl_xor_sync(0xffffffffu, ws[i], 2);
        }
        float* wrowW = wrow + wid * 16;
        if ((lane & 3) == 0) {
            int r = lane >> 2;
            wrowW[r] = ws[0];
            wrowW[r + 8] = ws[1];
        }
        __syncwarp();

        // per-point finish (lanes 0-15, one point each)
        float contrib = 0.f, mval = 0.f;
        if (wvalid && lane < 16) {
            float w = wrowW[lane] + b3v;
            size_t gi = (size_t)t * NN + p0 + wid * 16 + lane;
            float mf = (mask_kind == 0) ? (float)mask_raw[gi]
                     : (mask_kind == 1) ? (float)((const int*)mask_raw)[gi]
                     : ((const float*)mask_raw)[gi];
            float wm = w * mf;
            out_w[gi] = wm;
            contrib = wm * rets[gi];
            mval = mf;
        }
#pragma unroll
        for (int off = 16; off; off >>= 1) {
            contrib += __shfl_down_sync(0xffffffffu, contrib, off);
            mval    += __shfl_down_sync(0xffffffffu, mval, off);
        }
        if (lane == 0 && wvalid) {
            atomicAdd(&g_sum[t], contrib);
            atomicAdd(&g_cnt[t], mval);
        }
    }

    // ---- inlined finalize: last CTA computes sdf ----
    __shared__ unsigned s_last;
    __threadfence();
    __syncthreads();
    if (tid == 0) s_last = (atomicAdd(&g_done, 1u) == (unsigned)(gridDim.x - 1));
    __syncthreads();
    if (s_last) {
        __threadfence();
        float* red = wrow;
        float cnt = __ldcg(&g_cnt[tid]);
        float sum = __ldcg(&g_sum[tid]);
        float csum = cnt;
#pragma unroll
        for (int off = 16; off; off >>= 1)
            csum += __shfl_xor_sync(0xffffffffu, csum, off);
        if (lane == 0) red[wid] = csum;
        __syncthreads();
        float mean = (((red[0] + red[1]) + (red[2] + red[3])) +
                      ((red[4] + red[5]) + (red[6] + red[7]))) * (1.0f / 256.0f);
        out_sdf[tid] = sum / cnt * mean + 1.0f;
    }
}

// ---------- launch ----------
extern "C" void kernel_launch(void* const* d_in, const int* in_sizes, int n_in,
                              void* d_out, int out_size) {
    (void)in_sizes; (void)n_in; (void)out_size;
    const float* macro = (const float*)d_in[0];
    const float* indiv = (const float*)d_in[1];
    const unsigned char* masks = (const unsigned char*)d_in[2];
    const float* rets  = (const float*)d_in[3];
    const float* W_ih  = (const float*)d_in[4];
    const float* W_hh  = (const float*)d_in[5];
    const float* b_ih  = (const float*)d_in[6];
    const float* b_hh  = (const float*)d_in[7];
    const float* W1    = (const float*)d_in[8];
    const float* b1    = (const float*)d_in[9];
    const float* W2    = (const float*)d_in[10];
    const float* b2    = (const float*)d_in[11];
    const float* W3    = (const float*)d_in[12];
    const float* b3    = (const float*)d_in[13];

    float* out     = (float*)d_out;
    float* out_sdf = out;          // sdf [T,1]
    float* out_w   = out + T_;     // weights [1,T,N,1]

    cudaFuncSetAttribute(k_prep, cudaFuncAttributeMaxDynamicSharedMemorySize, PREP_SMEM);
    cudaFuncSetAttribute(k_lstm, cudaFuncAttributeMaxDynamicSharedMemorySize, LSTM_SMEM);
    cudaFuncSetAttribute(k_mlp,  cudaFuncAttributeMaxDynamicSharedMemorySize, SMEM_MLP);

    k_prep<<<256, 256, PREP_SMEM>>>(macro, W_ih, b_ih, b_hh, masks);
    k_lstm<<<1, 256, LSTM_SMEM>>>(W_hh, W1, b1);
    k_mlp<<<GRID_MLP, 256, SMEM_MLP>>>(indiv, masks, rets, W1, W2, b2, W3, b3,
                                       out_w, out_sdf);
}